// round 12
// baseline (speedup 1.0000x reference)
#include <cuda_runtime.h>
#include <cuda_bf16.h>
#include <cuda_fp16.h>
#include <cstdint>

// ---------------------------------------------------------------------------
// GraphAttentionLayer on GB300 (sm_103a; harness PTX target lacks 'a' suffix,
// so tcgen05 unavailable -> mma.sync).
//  G      : G = W1 W2^T fp32 (tiny), split to bf16 hi/lo (gt layout [n][k])
//  proj   : 3x-bf16 mma m16n8k16: z=0 -> Y = X G (bf16 hi/lo), z=1 -> h3 fp16
//  scores : e = Y X^T, 3x-bf16 mma 128x128 tile; epilogue stores
//           p_t = fp16(exp(e - m_tile)) + per-tile softmax partials
//  AV     : stages p_t; in-kernel softmax stats; A fragments scaled in
//           registers by exp(m_tile-m_row)/s_row; fp16 mma, relu
// ---------------------------------------------------------------------------

#define ALPHA_SLOPE 0.2f
#define NEG_INF_F  -1.0e12f

#define BB   8
#define NSEQ 2048
#define CDIM 256
#define M_ALL (BB * NSEQ)        // 16384
#define NTILES 16                // NSEQ / 128

#define BM 128
#define BN 128
#define NTHR 256

// ---- bf16 GEMM tile geometry (proj & scores), BK=32 ----
#define BKS 32
#define SP  40                   // bf16 pitch (80B) -> LDSM conflict-free
#define STILE (BM * SP)          // 5120 bf16 per array
#define SA_H 0
#define SA_L STILE
#define SB_H (2 * STILE)
#define SB_L (3 * STILE)
#define SSTG (4 * STILE)         // 20480 bf16 = 40960 B / stage

// ---- AV geometry: BM=64, BN=256, BK=32 ----
#define AV_BM 64
#define APT 40                                // p_t stage pitch (fp16)
#define AV_A_BYTES (AV_BM * APT * 2)          // 5120
#define BKP2 264                              // h3 tile pitch (fp16, 256+8)
#define AV_B_BYTES (BKS * BKP2 * 2)           // 16896
#define AV_STG2 (AV_A_BYTES + AV_B_BYTES)     // 22016
#define AV_NSTG 4
#define AV_STAB (AV_NSTG * AV_STG2)           // 88064
#define SM_AV (AV_STAB + AV_BM * NTILES * 4)  // + 4KB scale table = 92160

// ---- global scratch ----
__device__ __nv_bfloat16 g_xbH[(size_t)M_ALL * CDIM];
__device__ __nv_bfloat16 g_xbL[(size_t)M_ALL * CDIM];
__device__ __nv_bfloat16 g_wtH[2 * CDIM * CDIM];       // slot0: gt=(W1W2^T)^T, slot1: W3^T
__device__ __nv_bfloat16 g_wtL[2 * CDIM * CDIM];
__device__ __nv_bfloat16 g_hbH[(size_t)M_ALL * CDIM];  // Y bf16 hi
__device__ __nv_bfloat16 g_hbL[(size_t)M_ALL * CDIM];  // Y bf16 lo
__device__ __half g_h316[(size_t)M_ALL * CDIM];        // h3 fp16
__device__ __half g_pt[(size_t)BB * NSEQ * NSEQ];      // p_t = exp(e - m_tile) fp16
__device__ float g_pm[(size_t)BB * NTILES * NSEQ];     // per-tile row max
__device__ float g_ps[(size_t)BB * NTILES * NSEQ];     // per-tile row sum-exp

// ---------------- helpers ----------------
__device__ __forceinline__ void mma_bf16(float c[4],
                                         uint32_t a0, uint32_t a1, uint32_t a2, uint32_t a3,
                                         uint32_t b0, uint32_t b1) {
    asm volatile(
        "mma.sync.aligned.m16n8k16.row.col.f32.bf16.bf16.f32 "
        "{%0,%1,%2,%3}, {%4,%5,%6,%7}, {%8,%9}, {%0,%1,%2,%3};\n"
        : "+f"(c[0]), "+f"(c[1]), "+f"(c[2]), "+f"(c[3])
        : "r"(a0), "r"(a1), "r"(a2), "r"(a3), "r"(b0), "r"(b1));
}

__device__ __forceinline__ void mma_fp16(float c[4],
                                         uint32_t a0, uint32_t a1, uint32_t a2, uint32_t a3,
                                         uint32_t b0, uint32_t b1) {
    asm volatile(
        "mma.sync.aligned.m16n8k16.row.col.f32.f16.f16.f32 "
        "{%0,%1,%2,%3}, {%4,%5,%6,%7}, {%8,%9}, {%0,%1,%2,%3};\n"
        : "+f"(c[0]), "+f"(c[1]), "+f"(c[2]), "+f"(c[3])
        : "r"(a0), "r"(a1), "r"(a2), "r"(a3), "r"(b0), "r"(b1));
}

__device__ __forceinline__ void ldsm_x4(uint32_t &r0, uint32_t &r1, uint32_t &r2, uint32_t &r3,
                                        uint32_t addr) {
    asm volatile("ldmatrix.sync.aligned.m8n8.x4.shared.b16 {%0,%1,%2,%3}, [%4];\n"
        : "=r"(r0), "=r"(r1), "=r"(r2), "=r"(r3) : "r"(addr));
}

__device__ __forceinline__ void ldsm_x4_t(uint32_t &r0, uint32_t &r1, uint32_t &r2, uint32_t &r3,
                                          uint32_t addr) {
    asm volatile("ldmatrix.sync.aligned.m8n8.x4.trans.shared.b16 {%0,%1,%2,%3}, [%4];\n"
        : "=r"(r0), "=r"(r1), "=r"(r2), "=r"(r3) : "r"(addr));
}

__device__ __forceinline__ void cpa16(uint32_t dst, const void* src) {
    asm volatile("cp.async.cg.shared.global [%0], [%1], 16;\n" :: "r"(dst), "l"(src) : "memory");
}
__device__ __forceinline__ void cpa_commit() {
    asm volatile("cp.async.commit_group;\n" ::: "memory");
}
template<int N>
__device__ __forceinline__ void cpa_wait() {
    asm volatile("cp.async.wait_group %0;\n" :: "n"(N) : "memory");
}

__device__ __forceinline__ uint32_t smem_u32(const void* p) {
    uint32_t a;
    asm("{ .reg .u64 t; cvta.to.shared.u64 t, %1; cvt.u32.u64 %0, t; }" : "=r"(a) : "l"(p));
    return a;
}

__device__ __forceinline__ void bsplit(float v, __nv_bfloat16 &h, __nv_bfloat16 &l) {
    h = __float2bfloat16_rn(v);
    l = __float2bfloat16_rn(v - __bfloat162float(h));
}

__device__ __forceinline__ uint32_t hmul2_u(uint32_t a, __half2 s) {
    __half2 v = *(__half2*)&a;
    v = __hmul2(v, s);
    return *(uint32_t*)&v;
}

// ---------------- prep kernels ----------------
__global__ void __launch_bounds__(256)
split_x_bf16(const float* __restrict__ src,
             __nv_bfloat16* __restrict__ H, __nv_bfloat16* __restrict__ L, int n4)
{
    int i = blockIdx.x * blockDim.x + threadIdx.x;
    if (i >= n4) return;
    float4 v = ((const float4*)src)[i];
    __nv_bfloat16 h0, h1, h2, h3, l0, l1, l2, l3;
    bsplit(v.x, h0, l0); bsplit(v.y, h1, l1);
    bsplit(v.z, h2, l2); bsplit(v.w, h3, l3);
    ((__nv_bfloat162*)H)[2 * i]     = __nv_bfloat162(h0, h1);
    ((__nv_bfloat162*)H)[2 * i + 1] = __nv_bfloat162(h2, h3);
    ((__nv_bfloat162*)L)[2 * i]     = __nv_bfloat162(l0, l1);
    ((__nv_bfloat162*)L)[2 * i + 1] = __nv_bfloat162(l2, l3);
}

// gt[n][k] = G[k][n] = sum_d W1[k][d] * W2[n][d]  -> slot 0 of g_wt*
__global__ void __launch_bounds__(256)
gt_kernel(const float* __restrict__ W1, const float* __restrict__ W2,
          __nv_bfloat16* __restrict__ H, __nv_bfloat16* __restrict__ L)
{
    const int n = blockIdx.x;       // 0..255
    const int k = threadIdx.x;      // 0..255
    __shared__ float w2row[CDIM];
    w2row[k] = W2[n * CDIM + k];
    __syncthreads();
    const float* w1r = W1 + k * CDIM;
    float s = 0.f;
    #pragma unroll 8
    for (int d = 0; d < CDIM; d++) s += w1r[d] * w2row[d];
    __nv_bfloat16 h, l;
    bsplit(s, h, l);
    H[n * CDIM + k] = h;
    L[n * CDIM + k] = l;
}

// wt3[n][k] = W3[k][n]  -> slot 1 of g_wt*
__global__ void __launch_bounds__(256)
wt3_kernel(const float* __restrict__ W3,
           __nv_bfloat16* __restrict__ H, __nv_bfloat16* __restrict__ L)
{
    const int idx = blockIdx.x * 256 + threadIdx.x;
    const int k = idx >> 8;
    const int n = idx & 255;
    float v = W3[k * CDIM + n];
    __nv_bfloat16 h, l;
    bsplit(v, h, l);
    const size_t o = (size_t)CDIM * CDIM + (size_t)n * CDIM + k;
    H[o - CDIM * CDIM + CDIM * CDIM] = h;   // slot 1
    L[o] = l;
    H[o] = h;
}

// ---------------- projection GEMM: 3x-bf16 m16n8k16 (128x128) ----------------
// z=0: Y = X @ G  -> bf16 hi/lo ; z=1: h3 = X @ W3 -> fp16
__global__ void __launch_bounds__(NTHR, 2)
proj_bf16(const __nv_bfloat16* __restrict__ xH, const __nv_bfloat16* __restrict__ xL,
          const __nv_bfloat16* __restrict__ wtH, const __nv_bfloat16* __restrict__ wtL,
          __nv_bfloat16* __restrict__ CbH, __nv_bfloat16* __restrict__ CbL,
          __half* __restrict__ C16)
{
    extern __shared__ __align__(16) __nv_bfloat16 smb[];
    constexpr int STAGES = 2;

    const int tid  = threadIdx.x;
    const int lane = tid & 31;
    const int warp = tid >> 5;
    const int wm = warp & 3, wn = warp >> 2;
    const int lr = lane >> 2, lc = lane & 3;
    const int n0 = blockIdx.x * BN;
    const int m0 = blockIdx.y * BM;
    const int z  = blockIdx.z;

    const __nv_bfloat16* A_H = xH + (size_t)m0 * CDIM;
    const __nv_bfloat16* A_L = xL + (size_t)m0 * CDIM;
    const __nv_bfloat16* B_H = wtH + (size_t)z * CDIM * CDIM + (size_t)n0 * CDIM;
    const __nv_bfloat16* B_L = wtL + (size_t)z * CDIM * CDIM + (size_t)n0 * CDIM;

    uint32_t sbase = smem_u32(smb);

    const int lrow = tid >> 1;
    const int lcb  = (tid & 1) * 16;
    const int qrow = lane & 15;
    const int qcol = (lane >> 4) << 3;

    auto issue = [&](int t) {
        const int buf = t % STAGES;
        const uint32_t sb = sbase + (uint32_t)(buf * SSTG) * 2u;
        const int kofs = t * BKS;
        const long long go0 = (long long)lrow * CDIM + kofs + lcb;
        const uint32_t d0 = (uint32_t)(lrow * SP + lcb) * 2u;
        cpa16(sb + (SA_H * 2u) + d0,      A_H + go0);
        cpa16(sb + (SA_H * 2u) + d0 + 16, A_H + go0 + 8);
        cpa16(sb + (SA_L * 2u) + d0,      A_L + go0);
        cpa16(sb + (SA_L * 2u) + d0 + 16, A_L + go0 + 8);
        cpa16(sb + (SB_H * 2u) + d0,      B_H + go0);
        cpa16(sb + (SB_H * 2u) + d0 + 16, B_H + go0 + 8);
        cpa16(sb + (SB_L * 2u) + d0,      B_L + go0);
        cpa16(sb + (SB_L * 2u) + d0 + 16, B_L + go0 + 8);
        cpa_commit();
    };

    float acc[2][8][4];
    #pragma unroll
    for (int i = 0; i < 2; i++)
        #pragma unroll
        for (int j = 0; j < 8; j++)
            #pragma unroll
            for (int q = 0; q < 4; q++) acc[i][j][q] = 0.f;

    const int T = CDIM / BKS;   // 8
    issue(0);

    for (int t = 0; t < T; t++) {
        cpa_wait<0>();
        __syncthreads();
        if (t + 1 < T) issue(t + 1); else cpa_commit();

        const int buf = t % STAGES;
        const uint32_t sb = sbase + (uint32_t)(buf * SSTG) * 2u;

        #pragma unroll
        for (int ks = 0; ks < 2; ks++) {
            const int kb = ks * 16;
            uint32_t aH[2][4], aL[2][4];
            #pragma unroll
            for (int mt = 0; mt < 2; mt++) {
                const uint32_t ro = (uint32_t)((wm * 32 + mt * 16 + qrow) * SP + kb + qcol) * 2u;
                ldsm_x4(aH[mt][0], aH[mt][1], aH[mt][2], aH[mt][3], sb + SA_H * 2u + ro);
                ldsm_x4(aL[mt][0], aL[mt][1], aL[mt][2], aL[mt][3], sb + SA_L * 2u + ro);
            }
            #pragma unroll
            for (int ng = 0; ng < 4; ng++) {
                const uint32_t bo = (uint32_t)((wn * 64 + ng * 16 + qrow) * SP + kb + qcol) * 2u;
                uint32_t bh[4], bl[4];
                ldsm_x4(bh[0], bh[1], bh[2], bh[3], sb + SB_H * 2u + bo);
                ldsm_x4(bl[0], bl[1], bl[2], bl[3], sb + SB_L * 2u + bo);
                #pragma unroll
                for (int sel = 0; sel < 2; sel++) {
                    const int nt = ng * 2 + sel;
                    const uint32_t bH0 = bh[sel], bH1 = bh[sel + 2];
                    const uint32_t bL0 = bl[sel], bL1 = bl[sel + 2];
                    #pragma unroll
                    for (int mt = 0; mt < 2; mt++) {
                        mma_bf16(acc[mt][nt], aH[mt][0], aH[mt][1], aH[mt][2], aH[mt][3], bL0, bL1);
                        mma_bf16(acc[mt][nt], aL[mt][0], aL[mt][1], aL[mt][2], aL[mt][3], bH0, bH1);
                        mma_bf16(acc[mt][nt], aH[mt][0], aH[mt][1], aH[mt][2], aH[mt][3], bH0, bH1);
                    }
                }
            }
        }
    }

    // ---- epilogue ----
    #pragma unroll
    for (int mt = 0; mt < 2; mt++) {
        #pragma unroll
        for (int nt = 0; nt < 8; nt++) {
            const int r0 = m0 + wm * 32 + mt * 16 + lr;
            const int c0 = n0 + wn * 64 + nt * 8 + lc * 2;
            if (z == 0) {
                #pragma unroll
                for (int rq = 0; rq < 2; rq++) {
                    const int r = r0 + rq * 8;
                    float v0 = acc[mt][nt][rq * 2 + 0];
                    float v1 = acc[mt][nt][rq * 2 + 1];
                    __nv_bfloat16 h0, l0, h1, l1;
                    bsplit(v0, h0, l0);
                    bsplit(v1, h1, l1);
                    const size_t o = (size_t)r * CDIM + c0;
                    *(__nv_bfloat162*)(CbH + o) = __nv_bfloat162(h0, h1);
                    *(__nv_bfloat162*)(CbL + o) = __nv_bfloat162(l0, l1);
                }
            } else {
                #pragma unroll
                for (int rq = 0; rq < 2; rq++) {
                    const int r = r0 + rq * 8;
                    const size_t o = (size_t)r * CDIM + c0;
                    *(__half2*)(C16 + o) =
                        __floats2half2_rn(acc[mt][nt][rq * 2 + 0], acc[mt][nt][rq * 2 + 1]);
                }
            }
        }
    }
}

// ---------------- scores GEMM: e = Y X^T, 3x-bf16, 128x128 tile ----------------
__global__ void __launch_bounds__(NTHR, 2)
scores_bf16(const __nv_bfloat16* __restrict__ yH, const __nv_bfloat16* __restrict__ yL,
            const __nv_bfloat16* __restrict__ xH, const __nv_bfloat16* __restrict__ xL,
            const int* __restrict__ adj, __half* __restrict__ pt,
            float* __restrict__ pm, float* __restrict__ ps)
{
    extern __shared__ __align__(16) __nv_bfloat16 smb[];
    constexpr int STAGES = 2;

    const int tid  = threadIdx.x;
    const int lane = tid & 31;
    const int warp = tid >> 5;
    const int wm = warp & 3, wn = warp >> 2;
    const int lr = lane >> 2, lc = lane & 3;
    const int n0 = blockIdx.x * BN;
    const int m0 = blockIdx.y * BM;
    const int z  = blockIdx.z;

    const long long BS = (long long)NSEQ * CDIM;
    const __nv_bfloat16* A_H = yH + z * BS + (long long)m0 * CDIM;
    const __nv_bfloat16* A_L = yL + z * BS + (long long)m0 * CDIM;
    const __nv_bfloat16* B_H = xH + z * BS + (long long)n0 * CDIM;
    const __nv_bfloat16* B_L = xL + z * BS + (long long)n0 * CDIM;

    uint32_t sbase = smem_u32(smb);

    const int lrow = tid >> 1;
    const int lcb  = (tid & 1) * 16;
    const int qrow = lane & 15;
    const int qcol = (lane >> 4) << 3;

    auto issue = [&](int t) {
        const int buf = t % STAGES;
        const uint32_t sb = sbase + (uint32_t)(buf * SSTG) * 2u;
        const int kofs = t * BKS;
        const long long go0 = (long long)lrow * CDIM + kofs + lcb;
        const uint32_t d0 = (uint32_t)(lrow * SP + lcb) * 2u;
        cpa16(sb + (SA_H * 2u) + d0,      A_H + go0);
        cpa16(sb + (SA_H * 2u) + d0 + 16, A_H + go0 + 8);
        cpa16(sb + (SA_L * 2u) + d0,      A_L + go0);
        cpa16(sb + (SA_L * 2u) + d0 + 16, A_L + go0 + 8);
        cpa16(sb + (SB_H * 2u) + d0,      B_H + go0);
        cpa16(sb + (SB_H * 2u) + d0 + 16, B_H + go0 + 8);
        cpa16(sb + (SB_L * 2u) + d0,      B_L + go0);
        cpa16(sb + (SB_L * 2u) + d0 + 16, B_L + go0 + 8);
        cpa_commit();
    };

    float acc[2][8][4];
    #pragma unroll
    for (int i = 0; i < 2; i++)
        #pragma unroll
        for (int j = 0; j < 8; j++)
            #pragma unroll
            for (int q = 0; q < 4; q++) acc[i][j][q] = 0.f;

    const int T = CDIM / BKS;   // 8
    issue(0);

    for (int t = 0; t < T; t++) {
        cpa_wait<0>();
        __syncthreads();
        if (t + 1 < T) issue(t + 1); else cpa_commit();

        const int buf = t % STAGES;
        const uint32_t sb = sbase + (uint32_t)(buf * SSTG) * 2u;

        #pragma unroll
        for (int ks = 0; ks < 2; ks++) {
            const int kb = ks * 16;
            uint32_t aH[2][4], aL[2][4];
            #pragma unroll
            for (int mt = 0; mt < 2; mt++) {
                const uint32_t ro = (uint32_t)((wm * 32 + mt * 16 + qrow) * SP + kb + qcol) * 2u;
                ldsm_x4(aH[mt][0], aH[mt][1], aH[mt][2], aH[mt][3], sb + SA_H * 2u + ro);
                ldsm_x4(aL[mt][0], aL[mt][1], aL[mt][2], aL[mt][3], sb + SA_L * 2u + ro);
            }
            #pragma unroll
            for (int ng = 0; ng < 4; ng++) {
                const uint32_t bo = (uint32_t)((wn * 64 + ng * 16 + qrow) * SP + kb + qcol) * 2u;
                uint32_t bh[4], bl[4];
                ldsm_x4(bh[0], bh[1], bh[2], bh[3], sb + SB_H * 2u + bo);
                ldsm_x4(bl[0], bl[1], bl[2], bl[3], sb + SB_L * 2u + bo);
                #pragma unroll
                for (int sel = 0; sel < 2; sel++) {
                    const int nt = ng * 2 + sel;
                    const uint32_t bH0 = bh[sel], bH1 = bh[sel + 2];
                    const uint32_t bL0 = bl[sel], bL1 = bl[sel + 2];
                    #pragma unroll
                    for (int mt = 0; mt < 2; mt++) {
                        mma_bf16(acc[mt][nt], aH[mt][0], aH[mt][1], aH[mt][2], aH[mt][3], bL0, bL1);
                        mma_bf16(acc[mt][nt], aL[mt][0], aL[mt][1], aL[mt][2], aL[mt][3], bH0, bH1);
                        mma_bf16(acc[mt][nt], aH[mt][0], aH[mt][1], aH[mt][2], aH[mt][3], bH0, bH1);
                    }
                }
            }
        }
    }

    // ---- epilogue pass A: leakyrelu + mask into acc, track per-row tile max ----
    float mx[2][2];
    mx[0][0] = mx[0][1] = mx[1][0] = mx[1][1] = -3.0e38f;
    #pragma unroll
    for (int mt = 0; mt < 2; mt++) {
        #pragma unroll
        for (int nt = 0; nt < 8; nt++) {
            const int r0 = m0 + wm * 32 + mt * 16 + lr;
            const int c0 = n0 + wn * 64 + nt * 8 + lc * 2;
            #pragma unroll
            for (int q = 0; q < 4; q++) {
                const int r = r0 + (q >> 1) * 8;
                const int c = c0 + (q & 1);
                float v = acc[mt][nt][q];
                v = (v > 0.f) ? v : ALPHA_SLOPE * v;
                v = (adj[(size_t)r * NSEQ + c] > 0) ? v : NEG_INF_F;
                acc[mt][nt][q] = v;
                mx[mt][q >> 1] = fmaxf(mx[mt][q >> 1], v);
            }
        }
    }

    // ---- tile-row max reduction ----
    float* red = reinterpret_cast<float*>(smb);
    __syncthreads();

    #pragma unroll
    for (int mt = 0; mt < 2; mt++)
        #pragma unroll
        for (int qr = 0; qr < 2; qr++) {
            float v = mx[mt][qr];
            v = fmaxf(v, __shfl_xor_sync(0xffffffffu, v, 1));
            v = fmaxf(v, __shfl_xor_sync(0xffffffffu, v, 2));
            mx[mt][qr] = v;
        }
    if (lc == 0) {
        #pragma unroll
        for (int mt = 0; mt < 2; mt++)
            #pragma unroll
            for (int qr = 0; qr < 2; qr++)
                red[wn * 128 + wm * 32 + mt * 16 + qr * 8 + lr] = mx[mt][qr];
    }
    __syncthreads();
    float M[2][2];
    #pragma unroll
    for (int mt = 0; mt < 2; mt++)
        #pragma unroll
        for (int qr = 0; qr < 2; qr++) {
            const int lro = wm * 32 + mt * 16 + qr * 8 + lr;
            M[mt][qr] = fmaxf(red[lro], red[128 + lro]);
        }
    __syncthreads();

    // ---- pass B: exp, store p_t fp16, accumulate sum partials ----
    __half* Pp = pt + (size_t)z * NSEQ * NSEQ;
    float Ss[2][2];
    #pragma unroll
    for (int mt = 0; mt < 2; mt++)
        #pragma unroll
        for (int qr = 0; qr < 2; qr++) {
            float s = 0.f;
            const int r = m0 + wm * 32 + mt * 16 + qr * 8 + lr;
            #pragma unroll
            for (int nt = 0; nt < 8; nt++) {
                float pe0 = __expf(acc[mt][nt][qr * 2 + 0] - M[mt][qr]);
                float pe1 = __expf(acc[mt][nt][qr * 2 + 1] - M[mt][qr]);
                s += pe0 + pe1;
                const int c = n0 + wn * 64 + nt * 8 + lc * 2;
                *(__half2*)(Pp + (size_t)r * NSEQ + c) = __floats2half2_rn(pe0, pe1);
            }
            s += __shfl_xor_sync(0xffffffffu, s, 1);
            s += __shfl_xor_sync(0xffffffffu, s, 2);
            Ss[mt][qr] = s;
        }
    if (lc == 0) {
        #pragma unroll
        for (int mt = 0; mt < 2; mt++)
            #pragma unroll
            for (int qr = 0; qr < 2; qr++)
                red[wn * 128 + wm * 32 + mt * 16 + qr * 8 + lr] = Ss[mt][qr];
    }
    __syncthreads();
    if (wn == 0 && lc == 0) {
        #pragma unroll
        for (int mt = 0; mt < 2; mt++)
            #pragma unroll
            for (int qr = 0; qr < 2; qr++) {
                const int lro = wm * 32 + mt * 16 + qr * 8 + lr;
                const size_t o = ((size_t)z * NTILES + blockIdx.x) * NSEQ + m0 + lro;
                pm[o] = M[mt][qr];
                ps[o] = red[lro] + red[128 + lro];
            }
    }
}

// ---------------- AV: p_t staged, register-scaled A fragments, fp16 mma ----------------
__global__ void __launch_bounds__(NTHR, 2)
av_fused(const __half* __restrict__ pt, const __half* __restrict__ h3,
         const float* __restrict__ pm, const float* __restrict__ ps,
         float* __restrict__ out)
{
    extern __shared__ __align__(16) uint8_t avs[];

    const int tid  = threadIdx.x;
    const int lane = tid & 31;
    const int warp = tid >> 5;
    const int wm = warp & 1;        // 2 warps over 64 rows
    const int wn = warp >> 1;       // 4 warps over 256 cols
    const int lr = lane >> 2, lc = lane & 3;
    const int m0 = blockIdx.x * AV_BM;
    const int z  = blockIdx.y;

    const __half* Ap = pt + (size_t)z * NSEQ * NSEQ + (size_t)m0 * NSEQ;
    const __half* Bp = h3 + (size_t)z * NSEQ * CDIM;

    uint32_t sbase = smem_u32(avs);

    const int qrow = lane & 15;
    const int qcol = (lane >> 4) << 3;

    // ---- per-row softmax stats + per-(row,tile) scale table (threads 0-63) ----
    __half2* stab = (__half2*)(avs + AV_STAB);
    if (tid < 64) {
        const int rr = tid;
        const float* pmz = pm + (size_t)z * NTILES * NSEQ + m0 + rr;
        const float* psz = ps + (size_t)z * NTILES * NSEQ + m0 + rr;
        float m = -3.0e38f;
        #pragma unroll
        for (int t = 0; t < NTILES; t++) m = fmaxf(m, pmz[(size_t)t * NSEQ]);
        float s = 0.f;
        #pragma unroll
        for (int t = 0; t < NTILES; t++)
            s += psz[(size_t)t * NSEQ] * __expf(pmz[(size_t)t * NSEQ] - m);
        const float inv = 1.0f / s;
        #pragma unroll
        for (int t = 0; t < NTILES; t++)
            stab[rr * NTILES + t] =
                __float2half2_rn(__expf(pmz[(size_t)t * NSEQ] - m) * inv);
    }

    const int crow = tid >> 2;      // 0..63
    const int cq   = tid & 3;

    auto issue = [&](int t) {
        const int buf = t % AV_NSTG;
        const uint32_t sA = sbase + (uint32_t)(buf * AV_STG2);
        const uint32_t sB = sA + AV_A_BYTES;
        const int kofs = t * BKS;
        {
            const __half* src = Ap + (size_t)crow * NSEQ + kofs + cq * 8;
            cpa16(sA + (uint32_t)(crow * APT + cq * 8) * 2u, src);
        }
        {
            const int brow = tid >> 3, bq = tid & 7;
            const __half* src = Bp + (size_t)(kofs + brow) * CDIM + bq * 32;
            const uint32_t d = sB + (uint32_t)(brow * BKP2 + bq * 32) * 2u;
            cpa16(d,      src);
            cpa16(d + 16, src + 8);
            cpa16(d + 32, src + 16);
            cpa16(d + 48, src + 24);
        }
        cpa_commit();
    };

    float acc[2][8][4];
    #pragma unroll
    for (int i = 0; i < 2; i++)
        #pragma unroll
        for (int j = 0; j < 8; j++)
            #pragma unroll
            for (int q = 0; q < 4; q++) acc[i][j][q] = 0.f;

    const int T = NSEQ / BKS;   // 64
    issue(0);
    issue(1);
    issue(2);
    __syncthreads();            // stab + ordering

    for (int t = 0; t < T; t++) {
        cpa_wait<AV_NSTG - 2>();
        __syncthreads();
        if (t + 3 < T) issue(t + 3); else cpa_commit();

        const uint32_t sA = sbase + (uint32_t)((t % AV_NSTG) * AV_STG2);
        const uint32_t sB = sA + AV_A_BYTES;
        const int kt = t >> 2;

        __half2 sc0[2], sc1[2];
        #pragma unroll
        for (int mt = 0; mt < 2; mt++) {
            const int base = wm * 32 + mt * 16;
            sc0[mt] = stab[(base + lr) * NTILES + kt];
            sc1[mt] = stab[(base + 8 + lr) * NTILES + kt];
        }

        #pragma unroll
        for (int ks = 0; ks < 2; ks++) {
            const int kb = ks * 16;
            uint32_t a[2][4];
            #pragma unroll
            for (int mt = 0; mt < 2; mt++) {
                const uint32_t ro = (uint32_t)((wm * 32 + mt * 16 + qrow) * APT + kb + qcol) * 2u;
                ldsm_x4(a[mt][0], a[mt][1], a[mt][2], a[mt][3], sA + ro);
                a[mt][0] = hmul2_u(a[mt][0], sc0[mt]);
                a[mt][2] = hmul2_u(a[mt][2], sc0[mt]);
                a[mt][1] = hmul2_u(a[mt][1], sc1[mt]);
                a[mt][3] = hmul2_u(a[mt][3], sc1[mt]);
            }
            #pragma unroll
            for (int ng = 0; ng < 4; ng++) {
                const int nb = wn * 64 + ng * 16;
                const uint32_t bo = (uint32_t)((kb + qrow) * BKP2 + nb + qcol) * 2u;
                uint32_t b[4];
                ldsm_x4_t(b[0], b[1], b[2], b[3], sB + bo);
                #pragma unroll
                for (int sel = 0; sel < 2; sel++) {
                    const int nt = ng * 2 + sel;
                    #pragma unroll
                    for (int mt = 0; mt < 2; mt++) {
                        mma_fp16(acc[mt][nt], a[mt][0], a[mt][1], a[mt][2], a[mt][3],
                                 b[2 * sel], b[2 * sel + 1]);
                    }
                }
            }
        }
    }

    // ---- epilogue: relu ----
    float* Cp = out + (size_t)z * NSEQ * CDIM;
    #pragma unroll
    for (int mt = 0; mt < 2; mt++) {
        #pragma unroll
        for (int nt = 0; nt < 8; nt++) {
            const int r0 = m0 + wm * 32 + mt * 16 + lr;
            const int c0 = wn * 64 + nt * 8 + lc * 2;
            #pragma unroll
            for (int q = 0; q < 4; q++) {
                const int r = r0 + (q >> 1) * 8;
                const int c = c0 + (q & 1);
                float v = acc[mt][nt][q];
                Cp[(size_t)r * CDIM + c] = (v > 0.f) ? v : 0.f;
            }
        }
    }
}

// ---------------- launcher ----------------
extern "C" void kernel_launch(void* const* d_in, const int* in_sizes, int n_in,
                              void* d_out, int out_size)
{
    const float* inp = (const float*)d_in[0];
    const int*   adj = (const int*)d_in[1];
    const float* W1  = (const float*)d_in[2];
    const float* W2  = (const float*)d_in[3];
    const float* W3  = (const float*)d_in[4];
    float* out = (float*)d_out;

    __nv_bfloat16 *xbH, *xbL, *wtH, *wtL, *hbH, *hbL;
    __half *h316, *pt;
    float *pm, *ps;
    cudaGetSymbolAddress((void**)&xbH,  g_xbH);
    cudaGetSymbolAddress((void**)&xbL,  g_xbL);
    cudaGetSymbolAddress((void**)&wtH,  g_wtH);
    cudaGetSymbolAddress((void**)&wtL,  g_wtL);
    cudaGetSymbolAddress((void**)&hbH,  g_hbH);
    cudaGetSymbolAddress((void**)&hbL,  g_hbL);
    cudaGetSymbolAddress((void**)&h316, g_h316);
    cudaGetSymbolAddress((void**)&pt,   g_pt);
    cudaGetSymbolAddress((void**)&pm,   g_pm);
    cudaGetSymbolAddress((void**)&ps,   g_ps);

    const int SM_BF = SSTG * 2 * 2;     // 81920 B
    cudaFuncSetAttribute(proj_bf16,   cudaFuncAttributeMaxDynamicSharedMemorySize, SM_BF);
    cudaFuncSetAttribute(scores_bf16, cudaFuncAttributeMaxDynamicSharedMemorySize, SM_BF);
    cudaFuncSetAttribute(av_fused,    cudaFuncAttributeMaxDynamicSharedMemorySize, SM_AV);

    // 0) split X; build gt = (W1 W2^T)^T and wt3 = W3^T (bf16 hi/lo)
    {
        const int xn4 = (int)((size_t)M_ALL * CDIM / 4);
        split_x_bf16<<<(xn4 + 255) / 256, 256>>>(inp, xbH, xbL, xn4);
        gt_kernel<<<CDIM, 256>>>(W1, W2, wtH, wtL);
        wt3_kernel<<<CDIM * CDIM / 256, 256>>>(W3, wtH, wtL);
    }
    // 1) projections: z=0 -> Y bf16 hi/lo; z=1 -> h3 fp16
    {
        dim3 g(CDIM / BN, M_ALL / BM, 2);
        proj_bf16<<<g, NTHR, SM_BF>>>(xbH, xbL, wtH, wtL, hbH, hbL, h316);
    }
    // 2) scores: e = Y X^T -> p_t fp16 + per-tile softmax partials
    {
        dim3 g(NSEQ / BN, NSEQ / BM, BB);
        scores_bf16<<<g, NTHR, SM_BF>>>(hbH, hbL, xbH, xbL, adj, pt, pm, ps);
    }
    // 3) AV with staged p_t, register scaling, in-kernel softmax stats
    {
        dim3 g(NSEQ / AV_BM, BB);
        av_fused<<<g, NTHR, SM_AV>>>(pt, h316, pm, ps, out);
    }
}

// round 13
// speedup vs baseline: 1.1316x; 1.1316x over previous
#include <cuda_runtime.h>
#include <cuda_bf16.h>
#include <cuda_fp16.h>
#include <cstdint>

// ---------------------------------------------------------------------------
// GraphAttentionLayer on GB300 (sm_103a; harness PTX target lacks 'a' suffix,
// so tcgen05 unavailable -> mma.sync).
//  G      : G = W1 W2^T via smem-tiled fp32 GEMM-T, split bf16 hi/lo ([n][k])
//  proj   : 3x-bf16 mma m16n8k16: z=0 -> Y = X G (bf16 hi/lo), z=1 -> h3 fp16
//  scores : e = Y X^T, 3x-bf16 mma 128x128 tile; epilogue stores
//           p_t = fp16(exp(e - m_tile)) + per-tile softmax partials
//  AV     : stages p_t; in-kernel softmax stats; A fragments scaled in
//           registers by exp(m_tile-m_row)/s_row; fp16 mma, relu
// ---------------------------------------------------------------------------

#define ALPHA_SLOPE 0.2f
#define NEG_INF_F  -1.0e12f

#define BB   8
#define NSEQ 2048
#define CDIM 256
#define M_ALL (BB * NSEQ)        // 16384
#define NTILES 16                // NSEQ / 128

#define BM 128
#define BN 128
#define NTHR 256

// ---- bf16 GEMM tile geometry (proj & scores), BK=32 ----
#define BKS 32
#define SP  40                   // bf16 pitch (80B) -> LDSM conflict-free
#define STILE (BM * SP)          // 5120 bf16 per array
#define SA_H 0
#define SA_L STILE
#define SB_H (2 * STILE)
#define SB_L (3 * STILE)
#define SSTG (4 * STILE)         // 20480 bf16 = 40960 B / stage

// ---- AV geometry: BM=64, BN=256, BK=32 ----
#define AV_BM 64
#define APT 40                                // p_t stage pitch (fp16)
#define AV_A_BYTES (AV_BM * APT * 2)          // 5120
#define BKP2 264                              // h3 tile pitch (fp16, 256+8)
#define AV_B_BYTES (BKS * BKP2 * 2)           // 16896
#define AV_STG2 (AV_A_BYTES + AV_B_BYTES)     // 22016
#define AV_NSTG 4
#define AV_STAB (AV_NSTG * AV_STG2)           // 88064
#define SM_AV (AV_STAB + AV_BM * NTILES * 4)  // + 4KB scale table = 92160

// ---- global scratch ----
__device__ __nv_bfloat16 g_xbH[(size_t)M_ALL * CDIM];
__device__ __nv_bfloat16 g_xbL[(size_t)M_ALL * CDIM];
__device__ __nv_bfloat16 g_wtH[2 * CDIM * CDIM];       // slot0: gt=(W1W2^T)^T, slot1: W3^T
__device__ __nv_bfloat16 g_wtL[2 * CDIM * CDIM];
__device__ __nv_bfloat16 g_hbH[(size_t)M_ALL * CDIM];  // Y bf16 hi
__device__ __nv_bfloat16 g_hbL[(size_t)M_ALL * CDIM];  // Y bf16 lo
__device__ __half g_h316[(size_t)M_ALL * CDIM];        // h3 fp16
__device__ __half g_pt[(size_t)BB * NSEQ * NSEQ];      // p_t = exp(e - m_tile) fp16
__device__ float g_pm[(size_t)BB * NTILES * NSEQ];     // per-tile row max
__device__ float g_ps[(size_t)BB * NTILES * NSEQ];     // per-tile row sum-exp

// ---------------- helpers ----------------
__device__ __forceinline__ void mma_bf16(float c[4],
                                         uint32_t a0, uint32_t a1, uint32_t a2, uint32_t a3,
                                         uint32_t b0, uint32_t b1) {
    asm volatile(
        "mma.sync.aligned.m16n8k16.row.col.f32.bf16.bf16.f32 "
        "{%0,%1,%2,%3}, {%4,%5,%6,%7}, {%8,%9}, {%0,%1,%2,%3};\n"
        : "+f"(c[0]), "+f"(c[1]), "+f"(c[2]), "+f"(c[3])
        : "r"(a0), "r"(a1), "r"(a2), "r"(a3), "r"(b0), "r"(b1));
}

__device__ __forceinline__ void mma_fp16(float c[4],
                                         uint32_t a0, uint32_t a1, uint32_t a2, uint32_t a3,
                                         uint32_t b0, uint32_t b1) {
    asm volatile(
        "mma.sync.aligned.m16n8k16.row.col.f32.f16.f16.f32 "
        "{%0,%1,%2,%3}, {%4,%5,%6,%7}, {%8,%9}, {%0,%1,%2,%3};\n"
        : "+f"(c[0]), "+f"(c[1]), "+f"(c[2]), "+f"(c[3])
        : "r"(a0), "r"(a1), "r"(a2), "r"(a3), "r"(b0), "r"(b1));
}

__device__ __forceinline__ void ldsm_x4(uint32_t &r0, uint32_t &r1, uint32_t &r2, uint32_t &r3,
                                        uint32_t addr) {
    asm volatile("ldmatrix.sync.aligned.m8n8.x4.shared.b16 {%0,%1,%2,%3}, [%4];\n"
        : "=r"(r0), "=r"(r1), "=r"(r2), "=r"(r3) : "r"(addr));
}

__device__ __forceinline__ void ldsm_x4_t(uint32_t &r0, uint32_t &r1, uint32_t &r2, uint32_t &r3,
                                          uint32_t addr) {
    asm volatile("ldmatrix.sync.aligned.m8n8.x4.trans.shared.b16 {%0,%1,%2,%3}, [%4];\n"
        : "=r"(r0), "=r"(r1), "=r"(r2), "=r"(r3) : "r"(addr));
}

__device__ __forceinline__ void cpa16(uint32_t dst, const void* src) {
    asm volatile("cp.async.cg.shared.global [%0], [%1], 16;\n" :: "r"(dst), "l"(src) : "memory");
}
__device__ __forceinline__ void cpa_commit() {
    asm volatile("cp.async.commit_group;\n" ::: "memory");
}
template<int N>
__device__ __forceinline__ void cpa_wait() {
    asm volatile("cp.async.wait_group %0;\n" :: "n"(N) : "memory");
}

__device__ __forceinline__ uint32_t smem_u32(const void* p) {
    uint32_t a;
    asm("{ .reg .u64 t; cvta.to.shared.u64 t, %1; cvt.u32.u64 %0, t; }" : "=r"(a) : "l"(p));
    return a;
}

__device__ __forceinline__ void bsplit(float v, __nv_bfloat16 &h, __nv_bfloat16 &l) {
    h = __float2bfloat16_rn(v);
    l = __float2bfloat16_rn(v - __bfloat162float(h));
}

__device__ __forceinline__ uint32_t hmul2_u(uint32_t a, __half2 s) {
    __half2 v = *(__half2*)&a;
    v = __hmul2(v, s);
    return *(uint32_t*)&v;
}

// ---------------- prep kernels ----------------
__global__ void __launch_bounds__(256)
split_x_bf16(const float* __restrict__ src,
             __nv_bfloat16* __restrict__ H, __nv_bfloat16* __restrict__ L, int n4)
{
    int i = blockIdx.x * blockDim.x + threadIdx.x;
    if (i >= n4) return;
    float4 v = ((const float4*)src)[i];
    __nv_bfloat16 h0, h1, h2, h3, l0, l1, l2, l3;
    bsplit(v.x, h0, l0); bsplit(v.y, h1, l1);
    bsplit(v.z, h2, l2); bsplit(v.w, h3, l3);
    ((__nv_bfloat162*)H)[2 * i]     = __nv_bfloat162(h0, h1);
    ((__nv_bfloat162*)H)[2 * i + 1] = __nv_bfloat162(h2, h3);
    ((__nv_bfloat162*)L)[2 * i]     = __nv_bfloat162(l0, l1);
    ((__nv_bfloat162*)L)[2 * i + 1] = __nv_bfloat162(l2, l3);
}

// gt[n][k] = G[k][n] = sum_d W1[k][d] * W2[n][d]   (smem-tiled, coalesced)
__global__ void __launch_bounds__(256)
gt_kernel(const float* __restrict__ W1, const float* __restrict__ W2,
          __nv_bfloat16* __restrict__ H, __nv_bfloat16* __restrict__ L)
{
    __shared__ float s1[64 * 33];   // W1 rows (k-dim), cols = d-chunk
    __shared__ float s2[64 * 33];   // W2 rows (n-dim)
    const int tid = threadIdx.x;
    const int k0 = blockIdx.x * 64;
    const int n0 = blockIdx.y * 64;
    const int tk = tid & 15;        // 16 k-subtiles
    const int tn = tid >> 4;        // 16 n-subtiles

    float acc[4][4] = {};
    for (int d0 = 0; d0 < CDIM; d0 += 32) {
        __syncthreads();
        #pragma unroll
        for (int i = 0; i < 8; i++) {
            const int idx = tid + i * 256;          // 0..2047
            const int row = idx >> 5, col = idx & 31;
            s1[row * 33 + col] = W1[(size_t)(k0 + row) * CDIM + d0 + col];
            s2[row * 33 + col] = W2[(size_t)(n0 + row) * CDIM + d0 + col];
        }
        __syncthreads();
        #pragma unroll
        for (int dd = 0; dd < 32; dd++) {
            float a[4], b[4];
            #pragma unroll
            for (int i = 0; i < 4; i++) a[i] = s2[(tn * 4 + i) * 33 + dd];
            #pragma unroll
            for (int j = 0; j < 4; j++) b[j] = s1[(tk * 4 + j) * 33 + dd];
            #pragma unroll
            for (int i = 0; i < 4; i++)
                #pragma unroll
                for (int j = 0; j < 4; j++) acc[i][j] += a[i] * b[j];
        }
    }
    #pragma unroll
    for (int i = 0; i < 4; i++)
        #pragma unroll
        for (int j = 0; j < 4; j++) {
            const int n = n0 + tn * 4 + i;
            const int k = k0 + tk * 4 + j;
            __nv_bfloat16 h, l;
            bsplit(acc[i][j], h, l);
            H[(size_t)n * CDIM + k] = h;
            L[(size_t)n * CDIM + k] = l;
        }
}

// wt3[n][k] = W3[k][n]  -> slot 1 of g_wt*
__global__ void __launch_bounds__(256)
wt3_kernel(const float* __restrict__ W3,
           __nv_bfloat16* __restrict__ H, __nv_bfloat16* __restrict__ L)
{
    const int idx = blockIdx.x * 256 + threadIdx.x;
    const int k = idx >> 8;
    const int n = idx & 255;
    float v = W3[k * CDIM + n];
    __nv_bfloat16 h, l;
    bsplit(v, h, l);
    const size_t o = (size_t)CDIM * CDIM + (size_t)n * CDIM + k;
    H[o] = h;
    L[o] = l;
}

// ---------------- projection GEMM: 3x-bf16 m16n8k16 (128x128) ----------------
// z=0: Y = X @ G  -> bf16 hi/lo ; z=1: h3 = X @ W3 -> fp16
__global__ void __launch_bounds__(NTHR, 2)
proj_bf16(const __nv_bfloat16* __restrict__ xH, const __nv_bfloat16* __restrict__ xL,
          const __nv_bfloat16* __restrict__ wtH, const __nv_bfloat16* __restrict__ wtL,
          __nv_bfloat16* __restrict__ CbH, __nv_bfloat16* __restrict__ CbL,
          __half* __restrict__ C16)
{
    extern __shared__ __align__(16) __nv_bfloat16 smb[];
    constexpr int STAGES = 2;

    const int tid  = threadIdx.x;
    const int lane = tid & 31;
    const int warp = tid >> 5;
    const int wm = warp & 3, wn = warp >> 2;
    const int lr = lane >> 2, lc = lane & 3;
    const int n0 = blockIdx.x * BN;
    const int m0 = blockIdx.y * BM;
    const int z  = blockIdx.z;

    const __nv_bfloat16* A_H = xH + (size_t)m0 * CDIM;
    const __nv_bfloat16* A_L = xL + (size_t)m0 * CDIM;
    const __nv_bfloat16* B_H = wtH + (size_t)z * CDIM * CDIM + (size_t)n0 * CDIM;
    const __nv_bfloat16* B_L = wtL + (size_t)z * CDIM * CDIM + (size_t)n0 * CDIM;

    uint32_t sbase = smem_u32(smb);

    const int lrow = tid >> 1;
    const int lcb  = (tid & 1) * 16;
    const int qrow = lane & 15;
    const int qcol = (lane >> 4) << 3;

    auto issue = [&](int t) {
        const int buf = t % STAGES;
        const uint32_t sb = sbase + (uint32_t)(buf * SSTG) * 2u;
        const int kofs = t * BKS;
        const long long go0 = (long long)lrow * CDIM + kofs + lcb;
        const uint32_t d0 = (uint32_t)(lrow * SP + lcb) * 2u;
        cpa16(sb + (SA_H * 2u) + d0,      A_H + go0);
        cpa16(sb + (SA_H * 2u) + d0 + 16, A_H + go0 + 8);
        cpa16(sb + (SA_L * 2u) + d0,      A_L + go0);
        cpa16(sb + (SA_L * 2u) + d0 + 16, A_L + go0 + 8);
        cpa16(sb + (SB_H * 2u) + d0,      B_H + go0);
        cpa16(sb + (SB_H * 2u) + d0 + 16, B_H + go0 + 8);
        cpa16(sb + (SB_L * 2u) + d0,      B_L + go0);
        cpa16(sb + (SB_L * 2u) + d0 + 16, B_L + go0 + 8);
        cpa_commit();
    };

    float acc[2][8][4];
    #pragma unroll
    for (int i = 0; i < 2; i++)
        #pragma unroll
        for (int j = 0; j < 8; j++)
            #pragma unroll
            for (int q = 0; q < 4; q++) acc[i][j][q] = 0.f;

    const int T = CDIM / BKS;   // 8
    issue(0);

    for (int t = 0; t < T; t++) {
        cpa_wait<0>();
        __syncthreads();
        if (t + 1 < T) issue(t + 1); else cpa_commit();

        const int buf = t % STAGES;
        const uint32_t sb = sbase + (uint32_t)(buf * SSTG) * 2u;

        #pragma unroll
        for (int ks = 0; ks < 2; ks++) {
            const int kb = ks * 16;
            uint32_t aH[2][4], aL[2][4];
            #pragma unroll
            for (int mt = 0; mt < 2; mt++) {
                const uint32_t ro = (uint32_t)((wm * 32 + mt * 16 + qrow) * SP + kb + qcol) * 2u;
                ldsm_x4(aH[mt][0], aH[mt][1], aH[mt][2], aH[mt][3], sb + SA_H * 2u + ro);
                ldsm_x4(aL[mt][0], aL[mt][1], aL[mt][2], aL[mt][3], sb + SA_L * 2u + ro);
            }
            #pragma unroll
            for (int ng = 0; ng < 4; ng++) {
                const uint32_t bo = (uint32_t)((wn * 64 + ng * 16 + qrow) * SP + kb + qcol) * 2u;
                uint32_t bh[4], bl[4];
                ldsm_x4(bh[0], bh[1], bh[2], bh[3], sb + SB_H * 2u + bo);
                ldsm_x4(bl[0], bl[1], bl[2], bl[3], sb + SB_L * 2u + bo);
                #pragma unroll
                for (int sel = 0; sel < 2; sel++) {
                    const int nt = ng * 2 + sel;
                    const uint32_t bH0 = bh[sel], bH1 = bh[sel + 2];
                    const uint32_t bL0 = bl[sel], bL1 = bl[sel + 2];
                    #pragma unroll
                    for (int mt = 0; mt < 2; mt++) {
                        mma_bf16(acc[mt][nt], aH[mt][0], aH[mt][1], aH[mt][2], aH[mt][3], bL0, bL1);
                        mma_bf16(acc[mt][nt], aL[mt][0], aL[mt][1], aL[mt][2], aL[mt][3], bH0, bH1);
                        mma_bf16(acc[mt][nt], aH[mt][0], aH[mt][1], aH[mt][2], aH[mt][3], bH0, bH1);
                    }
                }
            }
        }
    }

    // ---- epilogue ----
    #pragma unroll
    for (int mt = 0; mt < 2; mt++) {
        #pragma unroll
        for (int nt = 0; nt < 8; nt++) {
            const int r0 = m0 + wm * 32 + mt * 16 + lr;
            const int c0 = n0 + wn * 64 + nt * 8 + lc * 2;
            if (z == 0) {
                #pragma unroll
                for (int rq = 0; rq < 2; rq++) {
                    const int r = r0 + rq * 8;
                    float v0 = acc[mt][nt][rq * 2 + 0];
                    float v1 = acc[mt][nt][rq * 2 + 1];
                    __nv_bfloat16 h0, l0, h1, l1;
                    bsplit(v0, h0, l0);
                    bsplit(v1, h1, l1);
                    const size_t o = (size_t)r * CDIM + c0;
                    *(__nv_bfloat162*)(CbH + o) = __nv_bfloat162(h0, h1);
                    *(__nv_bfloat162*)(CbL + o) = __nv_bfloat162(l0, l1);
                }
            } else {
                #pragma unroll
                for (int rq = 0; rq < 2; rq++) {
                    const int r = r0 + rq * 8;
                    const size_t o = (size_t)r * CDIM + c0;
                    *(__half2*)(C16 + o) =
                        __floats2half2_rn(acc[mt][nt][rq * 2 + 0], acc[mt][nt][rq * 2 + 1]);
                }
            }
        }
    }
}

// ---------------- scores GEMM: e = Y X^T, 3x-bf16, 128x128 tile ----------------
__global__ void __launch_bounds__(NTHR, 2)
scores_bf16(const __nv_bfloat16* __restrict__ yH, const __nv_bfloat16* __restrict__ yL,
            const __nv_bfloat16* __restrict__ xH, const __nv_bfloat16* __restrict__ xL,
            const int* __restrict__ adj, __half* __restrict__ pt,
            float* __restrict__ pm, float* __restrict__ ps)
{
    extern __shared__ __align__(16) __nv_bfloat16 smb[];
    constexpr int STAGES = 2;

    const int tid  = threadIdx.x;
    const int lane = tid & 31;
    const int warp = tid >> 5;
    const int wm = warp & 3, wn = warp >> 2;
    const int lr = lane >> 2, lc = lane & 3;
    const int n0 = blockIdx.x * BN;
    const int m0 = blockIdx.y * BM;
    const int z  = blockIdx.z;

    const long long BS = (long long)NSEQ * CDIM;
    const __nv_bfloat16* A_H = yH + z * BS + (long long)m0 * CDIM;
    const __nv_bfloat16* A_L = yL + z * BS + (long long)m0 * CDIM;
    const __nv_bfloat16* B_H = xH + z * BS + (long long)n0 * CDIM;
    const __nv_bfloat16* B_L = xL + z * BS + (long long)n0 * CDIM;

    uint32_t sbase = smem_u32(smb);

    const int lrow = tid >> 1;
    const int lcb  = (tid & 1) * 16;
    const int qrow = lane & 15;
    const int qcol = (lane >> 4) << 3;

    auto issue = [&](int t) {
        const int buf = t % STAGES;
        const uint32_t sb = sbase + (uint32_t)(buf * SSTG) * 2u;
        const int kofs = t * BKS;
        const long long go0 = (long long)lrow * CDIM + kofs + lcb;
        const uint32_t d0 = (uint32_t)(lrow * SP + lcb) * 2u;
        cpa16(sb + (SA_H * 2u) + d0,      A_H + go0);
        cpa16(sb + (SA_H * 2u) + d0 + 16, A_H + go0 + 8);
        cpa16(sb + (SA_L * 2u) + d0,      A_L + go0);
        cpa16(sb + (SA_L * 2u) + d0 + 16, A_L + go0 + 8);
        cpa16(sb + (SB_H * 2u) + d0,      B_H + go0);
        cpa16(sb + (SB_H * 2u) + d0 + 16, B_H + go0 + 8);
        cpa16(sb + (SB_L * 2u) + d0,      B_L + go0);
        cpa16(sb + (SB_L * 2u) + d0 + 16, B_L + go0 + 8);
        cpa_commit();
    };

    float acc[2][8][4];
    #pragma unroll
    for (int i = 0; i < 2; i++)
        #pragma unroll
        for (int j = 0; j < 8; j++)
            #pragma unroll
            for (int q = 0; q < 4; q++) acc[i][j][q] = 0.f;

    const int T = CDIM / BKS;   // 8
    issue(0);

    for (int t = 0; t < T; t++) {
        cpa_wait<0>();
        __syncthreads();
        if (t + 1 < T) issue(t + 1); else cpa_commit();

        const int buf = t % STAGES;
        const uint32_t sb = sbase + (uint32_t)(buf * SSTG) * 2u;

        #pragma unroll
        for (int ks = 0; ks < 2; ks++) {
            const int kb = ks * 16;
            uint32_t aH[2][4], aL[2][4];
            #pragma unroll
            for (int mt = 0; mt < 2; mt++) {
                const uint32_t ro = (uint32_t)((wm * 32 + mt * 16 + qrow) * SP + kb + qcol) * 2u;
                ldsm_x4(aH[mt][0], aH[mt][1], aH[mt][2], aH[mt][3], sb + SA_H * 2u + ro);
                ldsm_x4(aL[mt][0], aL[mt][1], aL[mt][2], aL[mt][3], sb + SA_L * 2u + ro);
            }
            #pragma unroll
            for (int ng = 0; ng < 4; ng++) {
                const uint32_t bo = (uint32_t)((wn * 64 + ng * 16 + qrow) * SP + kb + qcol) * 2u;
                uint32_t bh[4], bl[4];
                ldsm_x4(bh[0], bh[1], bh[2], bh[3], sb + SB_H * 2u + bo);
                ldsm_x4(bl[0], bl[1], bl[2], bl[3], sb + SB_L * 2u + bo);
                #pragma unroll
                for (int sel = 0; sel < 2; sel++) {
                    const int nt = ng * 2 + sel;
                    const uint32_t bH0 = bh[sel], bH1 = bh[sel + 2];
                    const uint32_t bL0 = bl[sel], bL1 = bl[sel + 2];
                    #pragma unroll
                    for (int mt = 0; mt < 2; mt++) {
                        mma_bf16(acc[mt][nt], aH[mt][0], aH[mt][1], aH[mt][2], aH[mt][3], bL0, bL1);
                        mma_bf16(acc[mt][nt], aL[mt][0], aL[mt][1], aL[mt][2], aL[mt][3], bH0, bH1);
                        mma_bf16(acc[mt][nt], aH[mt][0], aH[mt][1], aH[mt][2], aH[mt][3], bH0, bH1);
                    }
                }
            }
        }
    }

    // ---- epilogue pass A: leakyrelu + mask into acc, track per-row tile max ----
    float mx[2][2];
    mx[0][0] = mx[0][1] = mx[1][0] = mx[1][1] = -3.0e38f;
    #pragma unroll
    for (int mt = 0; mt < 2; mt++) {
        #pragma unroll
        for (int nt = 0; nt < 8; nt++) {
            const int r0 = m0 + wm * 32 + mt * 16 + lr;
            const int c0 = n0 + wn * 64 + nt * 8 + lc * 2;
            #pragma unroll
            for (int q = 0; q < 4; q++) {
                const int r = r0 + (q >> 1) * 8;
                const int c = c0 + (q & 1);
                float v = acc[mt][nt][q];
                v = (v > 0.f) ? v : ALPHA_SLOPE * v;
                v = (adj[(size_t)r * NSEQ + c] > 0) ? v : NEG_INF_F;
                acc[mt][nt][q] = v;
                mx[mt][q >> 1] = fmaxf(mx[mt][q >> 1], v);
            }
        }
    }

    // ---- tile-row max reduction ----
    float* red = reinterpret_cast<float*>(smb);
    __syncthreads();

    #pragma unroll
    for (int mt = 0; mt < 2; mt++)
        #pragma unroll
        for (int qr = 0; qr < 2; qr++) {
            float v = mx[mt][qr];
            v = fmaxf(v, __shfl_xor_sync(0xffffffffu, v, 1));
            v = fmaxf(v, __shfl_xor_sync(0xffffffffu, v, 2));
            mx[mt][qr] = v;
        }
    if (lc == 0) {
        #pragma unroll
        for (int mt = 0; mt < 2; mt++)
            #pragma unroll
            for (int qr = 0; qr < 2; qr++)
                red[wn * 128 + wm * 32 + mt * 16 + qr * 8 + lr] = mx[mt][qr];
    }
    __syncthreads();
    float M[2][2];
    #pragma unroll
    for (int mt = 0; mt < 2; mt++)
        #pragma unroll
        for (int qr = 0; qr < 2; qr++) {
            const int lro = wm * 32 + mt * 16 + qr * 8 + lr;
            M[mt][qr] = fmaxf(red[lro], red[128 + lro]);
        }
    __syncthreads();

    // ---- pass B: exp, store p_t fp16, accumulate sum partials ----
    __half* Pp = pt + (size_t)z * NSEQ * NSEQ;
    float Ss[2][2];
    #pragma unroll
    for (int mt = 0; mt < 2; mt++)
        #pragma unroll
        for (int qr = 0; qr < 2; qr++) {
            float s = 0.f;
            const int r = m0 + wm * 32 + mt * 16 + qr * 8 + lr;
            #pragma unroll
            for (int nt = 0; nt < 8; nt++) {
                float pe0 = __expf(acc[mt][nt][qr * 2 + 0] - M[mt][qr]);
                float pe1 = __expf(acc[mt][nt][qr * 2 + 1] - M[mt][qr]);
                s += pe0 + pe1;
                const int c = n0 + wn * 64 + nt * 8 + lc * 2;
                *(__half2*)(Pp + (size_t)r * NSEQ + c) = __floats2half2_rn(pe0, pe1);
            }
            s += __shfl_xor_sync(0xffffffffu, s, 1);
            s += __shfl_xor_sync(0xffffffffu, s, 2);
            Ss[mt][qr] = s;
        }
    if (lc == 0) {
        #pragma unroll
        for (int mt = 0; mt < 2; mt++)
            #pragma unroll
            for (int qr = 0; qr < 2; qr++)
                red[wn * 128 + wm * 32 + mt * 16 + qr * 8 + lr] = Ss[mt][qr];
    }
    __syncthreads();
    if (wn == 0 && lc == 0) {
        #pragma unroll
        for (int mt = 0; mt < 2; mt++)
            #pragma unroll
            for (int qr = 0; qr < 2; qr++) {
                const int lro = wm * 32 + mt * 16 + qr * 8 + lr;
                const size_t o = ((size_t)z * NTILES + blockIdx.x) * NSEQ + m0 + lro;
                pm[o] = M[mt][qr];
                ps[o] = red[lro] + red[128 + lro];
            }
    }
}

// ---------------- AV: p_t staged, register-scaled A fragments, fp16 mma ----------------
__global__ void __launch_bounds__(NTHR, 2)
av_fused(const __half* __restrict__ pt, const __half* __restrict__ h3,
         const float* __restrict__ pm, const float* __restrict__ ps,
         float* __restrict__ out)
{
    extern __shared__ __align__(16) uint8_t avs[];

    const int tid  = threadIdx.x;
    const int lane = tid & 31;
    const int warp = tid >> 5;
    const int wm = warp & 1;        // 2 warps over 64 rows
    const int wn = warp >> 1;       // 4 warps over 256 cols
    const int lr = lane >> 2, lc = lane & 3;
    const int m0 = blockIdx.x * AV_BM;
    const int z  = blockIdx.y;

    const __half* Ap = pt + (size_t)z * NSEQ * NSEQ + (size_t)m0 * NSEQ;
    const __half* Bp = h3 + (size_t)z * NSEQ * CDIM;

    uint32_t sbase = smem_u32(avs);

    const int qrow = lane & 15;
    const int qcol = (lane >> 4) << 3;

    // ---- per-row softmax stats + per-(row,tile) scale table (threads 0-63) ----
    __half2* stab = (__half2*)(avs + AV_STAB);
    if (tid < 64) {
        const int rr = tid;
        const float* pmz = pm + (size_t)z * NTILES * NSEQ + m0 + rr;
        const float* psz = ps + (size_t)z * NTILES * NSEQ + m0 + rr;
        float m = -3.0e38f;
        #pragma unroll
        for (int t = 0; t < NTILES; t++) m = fmaxf(m, pmz[(size_t)t * NSEQ]);
        float s = 0.f;
        #pragma unroll
        for (int t = 0; t < NTILES; t++)
            s += psz[(size_t)t * NSEQ] * __expf(pmz[(size_t)t * NSEQ] - m);
        const float inv = 1.0f / s;
        #pragma unroll
        for (int t = 0; t < NTILES; t++)
            stab[rr * NTILES + t] =
                __float2half2_rn(__expf(pmz[(size_t)t * NSEQ] - m) * inv);
    }

    const int crow = tid >> 2;      // 0..63
    const int cq   = tid & 3;

    auto issue = [&](int t) {
        const int buf = t % AV_NSTG;
        const uint32_t sA = sbase + (uint32_t)(buf * AV_STG2);
        const uint32_t sB = sA + AV_A_BYTES;
        const int kofs = t * BKS;
        {
            const __half* src = Ap + (size_t)crow * NSEQ + kofs + cq * 8;
            cpa16(sA + (uint32_t)(crow * APT + cq * 8) * 2u, src);
        }
        {
            const int brow = tid >> 3, bq = tid & 7;
            const __half* src = Bp + (size_t)(kofs + brow) * CDIM + bq * 32;
            const uint32_t d = sB + (uint32_t)(brow * BKP2 + bq * 32) * 2u;
            cpa16(d,      src);
            cpa16(d + 16, src + 8);
            cpa16(d + 32, src + 16);
            cpa16(d + 48, src + 24);
        }
        cpa_commit();
    };

    float acc[2][8][4];
    #pragma unroll
    for (int i = 0; i < 2; i++)
        #pragma unroll
        for (int j = 0; j < 8; j++)
            #pragma unroll
            for (int q = 0; q < 4; q++) acc[i][j][q] = 0.f;

    const int T = NSEQ / BKS;   // 64
    issue(0);
    issue(1);
    issue(2);
    __syncthreads();            // stab + ordering

    for (int t = 0; t < T; t++) {
        cpa_wait<AV_NSTG - 2>();
        __syncthreads();
        if (t + 3 < T) issue(t + 3); else cpa_commit();

        const uint32_t sA = sbase + (uint32_t)((t % AV_NSTG) * AV_STG2);
        const uint32_t sB = sA + AV_A_BYTES;
        const int kt = t >> 2;

        __half2 sc0[2], sc1[2];
        #pragma unroll
        for (int mt = 0; mt < 2; mt++) {
            const int base = wm * 32 + mt * 16;
            sc0[mt] = stab[(base + lr) * NTILES + kt];
            sc1[mt] = stab[(base + 8 + lr) * NTILES + kt];
        }

        #pragma unroll
        for (int ks = 0; ks < 2; ks++) {
            const int kb = ks * 16;
            uint32_t a[2][4];
            #pragma unroll
            for (int mt = 0; mt < 2; mt++) {
                const uint32_t ro = (uint32_t)((wm * 32 + mt * 16 + qrow) * APT + kb + qcol) * 2u;
                ldsm_x4(a[mt][0], a[mt][1], a[mt][2], a[mt][3], sA + ro);
                a[mt][0] = hmul2_u(a[mt][0], sc0[mt]);
                a[mt][2] = hmul2_u(a[mt][2], sc0[mt]);
                a[mt][1] = hmul2_u(a[mt][1], sc1[mt]);
                a[mt][3] = hmul2_u(a[mt][3], sc1[mt]);
            }
            #pragma unroll
            for (int ng = 0; ng < 4; ng++) {
                const int nb = wn * 64 + ng * 16;
                const uint32_t bo = (uint32_t)((kb + qrow) * BKP2 + nb + qcol) * 2u;
                uint32_t b[4];
                ldsm_x4_t(b[0], b[1], b[2], b[3], sB + bo);
                #pragma unroll
                for (int sel = 0; sel < 2; sel++) {
                    const int nt = ng * 2 + sel;
                    #pragma unroll
                    for (int mt = 0; mt < 2; mt++) {
                        mma_fp16(acc[mt][nt], a[mt][0], a[mt][1], a[mt][2], a[mt][3],
                                 b[2 * sel], b[2 * sel + 1]);
                    }
                }
            }
        }
    }

    // ---- epilogue: relu ----
    float* Cp = out + (size_t)z * NSEQ * CDIM;
    #pragma unroll
    for (int mt = 0; mt < 2; mt++) {
        #pragma unroll
        for (int nt = 0; nt < 8; nt++) {
            const int r0 = m0 + wm * 32 + mt * 16 + lr;
            const int c0 = wn * 64 + nt * 8 + lc * 2;
            #pragma unroll
            for (int q = 0; q < 4; q++) {
                const int r = r0 + (q >> 1) * 8;
                const int c = c0 + (q & 1);
                float v = acc[mt][nt][q];
                Cp[(size_t)r * CDIM + c] = (v > 0.f) ? v : 0.f;
            }
        }
    }
}

// ---------------- launcher ----------------
extern "C" void kernel_launch(void* const* d_in, const int* in_sizes, int n_in,
                              void* d_out, int out_size)
{
    const float* inp = (const float*)d_in[0];
    const int*   adj = (const int*)d_in[1];
    const float* W1  = (const float*)d_in[2];
    const float* W2  = (const float*)d_in[3];
    const float* W3  = (const float*)d_in[4];
    float* out = (float*)d_out;

    __nv_bfloat16 *xbH, *xbL, *wtH, *wtL, *hbH, *hbL;
    __half *h316, *pt;
    float *pm, *ps;
    cudaGetSymbolAddress((void**)&xbH,  g_xbH);
    cudaGetSymbolAddress((void**)&xbL,  g_xbL);
    cudaGetSymbolAddress((void**)&wtH,  g_wtH);
    cudaGetSymbolAddress((void**)&wtL,  g_wtL);
    cudaGetSymbolAddress((void**)&hbH,  g_hbH);
    cudaGetSymbolAddress((void**)&hbL,  g_hbL);
    cudaGetSymbolAddress((void**)&h316, g_h316);
    cudaGetSymbolAddress((void**)&pt,   g_pt);
    cudaGetSymbolAddress((void**)&pm,   g_pm);
    cudaGetSymbolAddress((void**)&ps,   g_ps);

    const int SM_BF = SSTG * 2 * 2;     // 81920 B
    cudaFuncSetAttribute(proj_bf16,   cudaFuncAttributeMaxDynamicSharedMemorySize, SM_BF);
    cudaFuncSetAttribute(scores_bf16, cudaFuncAttributeMaxDynamicSharedMemorySize, SM_BF);
    cudaFuncSetAttribute(av_fused,    cudaFuncAttributeMaxDynamicSharedMemorySize, SM_AV);

    // 0) split X; build gt = (W1 W2^T)^T (tiled GEMM) and wt3 = W3^T
    {
        const int xn4 = (int)((size_t)M_ALL * CDIM / 4);
        split_x_bf16<<<(xn4 + 255) / 256, 256>>>(inp, xbH, xbL, xn4);
        dim3 gg(CDIM / 64, CDIM / 64);
        gt_kernel<<<gg, 256>>>(W1, W2, wtH, wtL);
        wt3_kernel<<<CDIM * CDIM / 256, 256>>>(W3, wtH, wtL);
    }
    // 1) projections: z=0 -> Y bf16 hi/lo; z=1 -> h3 fp16
    {
        dim3 g(CDIM / BN, M_ALL / BM, 2);
        proj_bf16<<<g, NTHR, SM_BF>>>(xbH, xbL, wtH, wtL, hbH, hbL, h316);
    }
    // 2) scores: e = Y X^T -> p_t fp16 + per-tile softmax partials
    {
        dim3 g(NSEQ / BN, NSEQ / BM, BB);
        scores_bf16<<<g, NTHR, SM_BF>>>(hbH, hbL, xbH, xbL, adj, pt, pm, ps);
    }
    // 3) AV with staged p_t, register scaling, in-kernel softmax stats
    {
        dim3 g(NSEQ / AV_BM, BB);
        av_fused<<<g, NTHR, SM_AV>>>(pt, h316, pm, ps, out);
    }
}

// round 16
// speedup vs baseline: 1.1667x; 1.0309x over previous
#include <cuda_runtime.h>
#include <cuda_bf16.h>
#include <cuda_fp16.h>
#include <cstdint>

// ---------------------------------------------------------------------------
// GraphAttentionLayer on GB300 (sm_103a; harness PTX target lacks 'a' suffix,
// so tcgen05 unavailable -> mma.sync).
//  G      : G = W1 W2^T via smem-tiled fp32 GEMM-T, split bf16 hi/lo ([n][k])
//  proj   : Y = X G via 3x-bf16 mma (128x128); h3 = X W3 via single-pass fp16
//  scores : e = Y X^T, 3x-bf16 mma 128x128 tile; epilogue stores
//           p_t = fp16(exp(e - m_tile)) + per-tile softmax partials
//  AV     : stages p_t; in-kernel softmax stats; A fragments scaled in
//           registers by exp(m_tile-m_row)/s_row; fp16 mma, relu
// ---------------------------------------------------------------------------

#define ALPHA_SLOPE 0.2f
#define NEG_INF_F  -1.0e12f

#define BB   8
#define NSEQ 2048
#define CDIM 256
#define M_ALL (BB * NSEQ)        // 16384
#define NTILES 16                // NSEQ / 128

#define BM 128
#define BN 128
#define NTHR 256

// ---- bf16/fp16 GEMM tile geometry, BK=32 ----
#define BKS 32
#define SP  40                   // 16-bit pitch (80B) -> LDSM conflict-free
#define STILE (BM * SP)          // 5120 elems per array
#define SA_H 0
#define SA_L STILE
#define SB_H (2 * STILE)
#define SB_L (3 * STILE)
#define SSTG (4 * STILE)         // 3x path: 40960 B / stage
#define P16_A 0
#define P16_B STILE
#define P16_STG (2 * STILE)      // fp16 path: 20480 B / stage

// ---- AV geometry: BM=64, BN=256, BK=32 ----
#define AV_BM 64
#define APT 40                                // p_t stage pitch (fp16)
#define AV_A_BYTES (AV_BM * APT * 2)          // 5120
#define BKP2 264                              // h3 tile pitch (fp16, 256+8)
#define AV_B_BYTES (BKS * BKP2 * 2)           // 16896
#define AV_STG2 (AV_A_BYTES + AV_B_BYTES)     // 22016
#define AV_NSTG 4
#define AV_STAB (AV_NSTG * AV_STG2)           // 88064
#define SM_AV (AV_STAB + AV_BM * NTILES * 4)  // + 4KB scale table = 92160

// ---- global scratch ----
__device__ __nv_bfloat16 g_xbH[(size_t)M_ALL * CDIM];
__device__ __nv_bfloat16 g_xbL[(size_t)M_ALL * CDIM];
__device__ __half g_x16[(size_t)M_ALL * CDIM];         // X fp16
__device__ __nv_bfloat16 g_wtH[CDIM * CDIM];           // gt=(W1W2^T)^T bf16 hi
__device__ __nv_bfloat16 g_wtL[CDIM * CDIM];
__device__ __half g_w316[CDIM * CDIM];                 // W3^T fp16 [n][k]
__device__ __nv_bfloat16 g_hbH[(size_t)M_ALL * CDIM];  // Y bf16 hi
__device__ __nv_bfloat16 g_hbL[(size_t)M_ALL * CDIM];  // Y bf16 lo
__device__ __half g_h316[(size_t)M_ALL * CDIM];        // h3 fp16
__device__ __half g_pt[(size_t)BB * NSEQ * NSEQ];      // p_t = exp(e - m_tile) fp16
__device__ float g_pm[(size_t)BB * NTILES * NSEQ];     // per-tile row max
__device__ float g_ps[(size_t)BB * NTILES * NSEQ];     // per-tile row sum-exp

// ---------------- helpers ----------------
__device__ __forceinline__ void mma_bf16(float c[4],
                                         uint32_t a0, uint32_t a1, uint32_t a2, uint32_t a3,
                                         uint32_t b0, uint32_t b1) {
    asm volatile(
        "mma.sync.aligned.m16n8k16.row.col.f32.bf16.bf16.f32 "
        "{%0,%1,%2,%3}, {%4,%5,%6,%7}, {%8,%9}, {%0,%1,%2,%3};\n"
        : "+f"(c[0]), "+f"(c[1]), "+f"(c[2]), "+f"(c[3])
        : "r"(a0), "r"(a1), "r"(a2), "r"(a3), "r"(b0), "r"(b1));
}

__device__ __forceinline__ void mma_fp16(float c[4],
                                         uint32_t a0, uint32_t a1, uint32_t a2, uint32_t a3,
                                         uint32_t b0, uint32_t b1) {
    asm volatile(
        "mma.sync.aligned.m16n8k16.row.col.f32.f16.f16.f32 "
        "{%0,%1,%2,%3}, {%4,%5,%6,%7}, {%8,%9}, {%0,%1,%2,%3};\n"
        : "+f"(c[0]), "+f"(c[1]), "+f"(c[2]), "+f"(c[3])
        : "r"(a0), "r"(a1), "r"(a2), "r"(a3), "r"(b0), "r"(b1));
}

__device__ __forceinline__ void ldsm_x4(uint32_t &r0, uint32_t &r1, uint32_t &r2, uint32_t &r3,
                                        uint32_t addr) {
    asm volatile("ldmatrix.sync.aligned.m8n8.x4.shared.b16 {%0,%1,%2,%3}, [%4];\n"
        : "=r"(r0), "=r"(r1), "=r"(r2), "=r"(r3) : "r"(addr));
}

__device__ __forceinline__ void ldsm_x4_t(uint32_t &r0, uint32_t &r1, uint32_t &r2, uint32_t &r3,
                                          uint32_t addr) {
    asm volatile("ldmatrix.sync.aligned.m8n8.x4.trans.shared.b16 {%0,%1,%2,%3}, [%4];\n"
        : "=r"(r0), "=r"(r1), "=r"(r2), "=r"(r3) : "r"(addr));
}

__device__ __forceinline__ void cpa16(uint32_t dst, const void* src) {
    asm volatile("cp.async.cg.shared.global [%0], [%1], 16;\n" :: "r"(dst), "l"(src) : "memory");
}
__device__ __forceinline__ void cpa_commit() {
    asm volatile("cp.async.commit_group;\n" ::: "memory");
}
template<int N>
__device__ __forceinline__ void cpa_wait() {
    asm volatile("cp.async.wait_group %0;\n" :: "n"(N) : "memory");
}

__device__ __forceinline__ uint32_t smem_u32(const void* p) {
    uint32_t a;
    asm("{ .reg .u64 t; cvta.to.shared.u64 t, %1; cvt.u32.u64 %0, t; }" : "=r"(a) : "l"(p));
    return a;
}

__device__ __forceinline__ void bsplit(float v, __nv_bfloat16 &h, __nv_bfloat16 &l) {
    h = __float2bfloat16_rn(v);
    l = __float2bfloat16_rn(v - __bfloat162float(h));
}

__device__ __forceinline__ uint32_t hmul2_u(uint32_t a, __half2 s) {
    __half2 v = *(__half2*)&a;
    v = __hmul2(v, s);
    return *(uint32_t*)&v;
}

// ---------------- prep kernels ----------------
__global__ void __launch_bounds__(256)
split_x_bf16(const float* __restrict__ src,
             __nv_bfloat16* __restrict__ H, __nv_bfloat16* __restrict__ L,
             __half* __restrict__ F16, int n4)
{
    int i = blockIdx.x * blockDim.x + threadIdx.x;
    if (i >= n4) return;
    float4 v = ((const float4*)src)[i];
    __nv_bfloat16 h0, h1, h2, h3, l0, l1, l2, l3;
    bsplit(v.x, h0, l0); bsplit(v.y, h1, l1);
    bsplit(v.z, h2, l2); bsplit(v.w, h3, l3);
    ((__nv_bfloat162*)H)[2 * i]     = __nv_bfloat162(h0, h1);
    ((__nv_bfloat162*)H)[2 * i + 1] = __nv_bfloat162(h2, h3);
    ((__nv_bfloat162*)L)[2 * i]     = __nv_bfloat162(l0, l1);
    ((__nv_bfloat162*)L)[2 * i + 1] = __nv_bfloat162(l2, l3);
    ((__half2*)F16)[2 * i]     = __floats2half2_rn(v.x, v.y);
    ((__half2*)F16)[2 * i + 1] = __floats2half2_rn(v.z, v.w);
}

// gt[n][k] = G[k][n] = sum_d W1[k][d] * W2[n][d]   (smem-tiled, coalesced)
__global__ void __launch_bounds__(256)
gt_kernel(const float* __restrict__ W1, const float* __restrict__ W2,
          __nv_bfloat16* __restrict__ H, __nv_bfloat16* __restrict__ L)
{
    __shared__ float s1[64 * 33];   // W1 rows (k-dim), cols = d-chunk
    __shared__ float s2[64 * 33];   // W2 rows (n-dim)
    const int tid = threadIdx.x;
    const int k0 = blockIdx.x * 64;
    const int n0 = blockIdx.y * 64;
    const int tk = tid & 15;
    const int tn = tid >> 4;

    float acc[4][4] = {};
    for (int d0 = 0; d0 < CDIM; d0 += 32) {
        __syncthreads();
        #pragma unroll
        for (int i = 0; i < 8; i++) {
            const int idx = tid + i * 256;
            const int row = idx >> 5, col = idx & 31;
            s1[row * 33 + col] = W1[(size_t)(k0 + row) * CDIM + d0 + col];
            s2[row * 33 + col] = W2[(size_t)(n0 + row) * CDIM + d0 + col];
        }
        __syncthreads();
        #pragma unroll
        for (int dd = 0; dd < 32; dd++) {
            float a[4], b[4];
            #pragma unroll
            for (int i = 0; i < 4; i++) a[i] = s2[(tn * 4 + i) * 33 + dd];
            #pragma unroll
            for (int j = 0; j < 4; j++) b[j] = s1[(tk * 4 + j) * 33 + dd];
            #pragma unroll
            for (int i = 0; i < 4; i++)
                #pragma unroll
                for (int j = 0; j < 4; j++) acc[i][j] += a[i] * b[j];
        }
    }
    #pragma unroll
    for (int i = 0; i < 4; i++)
        #pragma unroll
        for (int j = 0; j < 4; j++) {
            const int n = n0 + tn * 4 + i;
            const int k = k0 + tk * 4 + j;
            __nv_bfloat16 h, l;
            bsplit(acc[i][j], h, l);
            H[(size_t)n * CDIM + k] = h;
            L[(size_t)n * CDIM + k] = l;
        }
}

// w316[n][k] = fp16(W3[k][n])
__global__ void __launch_bounds__(256)
w316_kernel(const float* __restrict__ W3, __half* __restrict__ O)
{
    const int idx = blockIdx.x * 256 + threadIdx.x;
    const int k = idx >> 8;
    const int n = idx & 255;
    O[(size_t)n * CDIM + k] = __float2half_rn(W3[k * CDIM + n]);
}

// ---------------- proj Y: 3x-bf16 m16n8k16 (128x128) ----------------
__global__ void __launch_bounds__(NTHR, 2)
proj_bf16(const __nv_bfloat16* __restrict__ xH, const __nv_bfloat16* __restrict__ xL,
          const __nv_bfloat16* __restrict__ wtH, const __nv_bfloat16* __restrict__ wtL,
          __nv_bfloat16* __restrict__ CbH, __nv_bfloat16* __restrict__ CbL)
{
    extern __shared__ __align__(16) __nv_bfloat16 smb[];
    constexpr int STAGES = 2;

    const int tid  = threadIdx.x;
    const int lane = tid & 31;
    const int warp = tid >> 5;
    const int wm = warp & 3, wn = warp >> 2;
    const int lr = lane >> 2, lc = lane & 3;
    const int n0 = blockIdx.x * BN;
    const int m0 = blockIdx.y * BM;

    const __nv_bfloat16* A_H = xH + (size_t)m0 * CDIM;
    const __nv_bfloat16* A_L = xL + (size_t)m0 * CDIM;
    const __nv_bfloat16* B_H = wtH + (size_t)n0 * CDIM;
    const __nv_bfloat16* B_L = wtL + (size_t)n0 * CDIM;

    uint32_t sbase = smem_u32(smb);

    const int lrow = tid >> 1;
    const int lcb  = (tid & 1) * 16;
    const int qrow = lane & 15;
    const int qcol = (lane >> 4) << 3;

    auto issue = [&](int t) {
        const int buf = t % STAGES;
        const uint32_t sb = sbase + (uint32_t)(buf * SSTG) * 2u;
        const int kofs = t * BKS;
        const long long go0 = (long long)lrow * CDIM + kofs + lcb;
        const uint32_t d0 = (uint32_t)(lrow * SP + lcb) * 2u;
        cpa16(sb + (SA_H * 2u) + d0,      A_H + go0);
        cpa16(sb + (SA_H * 2u) + d0 + 16, A_H + go0 + 8);
        cpa16(sb + (SA_L * 2u) + d0,      A_L + go0);
        cpa16(sb + (SA_L * 2u) + d0 + 16, A_L + go0 + 8);
        cpa16(sb + (SB_H * 2u) + d0,      B_H + go0);
        cpa16(sb + (SB_H * 2u) + d0 + 16, B_H + go0 + 8);
        cpa16(sb + (SB_L * 2u) + d0,      B_L + go0);
        cpa16(sb + (SB_L * 2u) + d0 + 16, B_L + go0 + 8);
        cpa_commit();
    };

    float acc[2][8][4];
    #pragma unroll
    for (int i = 0; i < 2; i++)
        #pragma unroll
        for (int j = 0; j < 8; j++)
            #pragma unroll
            for (int q = 0; q < 4; q++) acc[i][j][q] = 0.f;

    const int T = CDIM / BKS;   // 8
    issue(0);

    for (int t = 0; t < T; t++) {
        cpa_wait<0>();
        __syncthreads();
        if (t + 1 < T) issue(t + 1); else cpa_commit();

        const int buf = t % STAGES;
        const uint32_t sb = sbase + (uint32_t)(buf * SSTG) * 2u;

        #pragma unroll
        for (int ks = 0; ks < 2; ks++) {
            const int kb = ks * 16;
            uint32_t aH[2][4], aL[2][4];
            #pragma unroll
            for (int mt = 0; mt < 2; mt++) {
                const uint32_t ro = (uint32_t)((wm * 32 + mt * 16 + qrow) * SP + kb + qcol) * 2u;
                ldsm_x4(aH[mt][0], aH[mt][1], aH[mt][2], aH[mt][3], sb + SA_H * 2u + ro);
                ldsm_x4(aL[mt][0], aL[mt][1], aL[mt][2], aL[mt][3], sb + SA_L * 2u + ro);
            }
            #pragma unroll
            for (int ng = 0; ng < 4; ng++) {
                const uint32_t bo = (uint32_t)((wn * 64 + ng * 16 + qrow) * SP + kb + qcol) * 2u;
                uint32_t bh[4], bl[4];
                ldsm_x4(bh[0], bh[1], bh[2], bh[3], sb + SB_H * 2u + bo);
                ldsm_x4(bl[0], bl[1], bl[2], bl[3], sb + SB_L * 2u + bo);
                #pragma unroll
                for (int sel = 0; sel < 2; sel++) {
                    const int nt = ng * 2 + sel;
                    const uint32_t bH0 = bh[sel], bH1 = bh[sel + 2];
                    const uint32_t bL0 = bl[sel], bL1 = bl[sel + 2];
                    #pragma unroll
                    for (int mt = 0; mt < 2; mt++) {
                        mma_bf16(acc[mt][nt], aH[mt][0], aH[mt][1], aH[mt][2], aH[mt][3], bL0, bL1);
                        mma_bf16(acc[mt][nt], aL[mt][0], aL[mt][1], aL[mt][2], aL[mt][3], bH0, bH1);
                        mma_bf16(acc[mt][nt], aH[mt][0], aH[mt][1], aH[mt][2], aH[mt][3], bH0, bH1);
                    }
                }
            }
        }
    }

    // ---- epilogue: split Y to bf16 hi/lo ----
    #pragma unroll
    for (int mt = 0; mt < 2; mt++) {
        #pragma unroll
        for (int nt = 0; nt < 8; nt++) {
            const int r0 = m0 + wm * 32 + mt * 16 + lr;
            const int c0 = n0 + wn * 64 + nt * 8 + lc * 2;
            #pragma unroll
            for (int rq = 0; rq < 2; rq++) {
                const int r = r0 + rq * 8;
                float v0 = acc[mt][nt][rq * 2 + 0];
                float v1 = acc[mt][nt][rq * 2 + 1];
                __nv_bfloat16 h0, l0, h1, l1;
                bsplit(v0, h0, l0);
                bsplit(v1, h1, l1);
                const size_t o = (size_t)r * CDIM + c0;
                *(__nv_bfloat162*)(CbH + o) = __nv_bfloat162(h0, h1);
                *(__nv_bfloat162*)(CbL + o) = __nv_bfloat162(l0, l1);
            }
        }
    }
}

// ---------------- proj h3: single-pass fp16 m16n8k16 (128x128) ----------------
__global__ void __launch_bounds__(NTHR, 2)
proj_fp16(const __half* __restrict__ x16, const __half* __restrict__ w316,
          __half* __restrict__ C16)
{
    extern __shared__ __align__(16) __half smh[];
    constexpr int STAGES = 2;

    const int tid  = threadIdx.x;
    const int lane = tid & 31;
    const int warp = tid >> 5;
    const int wm = warp & 3, wn = warp >> 2;
    const int lr = lane >> 2, lc = lane & 3;
    const int n0 = blockIdx.x * BN;
    const int m0 = blockIdx.y * BM;

    const __half* A_ = x16 + (size_t)m0 * CDIM;
    const __half* B_ = w316 + (size_t)n0 * CDIM;

    uint32_t sbase = smem_u32(smh);

    const int lrow = tid >> 1;
    const int lcb  = (tid & 1) * 16;
    const int qrow = lane & 15;
    const int qcol = (lane >> 4) << 3;

    auto issue = [&](int t) {
        const int buf = t % STAGES;
        const uint32_t sb = sbase + (uint32_t)(buf * P16_STG) * 2u;
        const int kofs = t * BKS;
        const long long go0 = (long long)lrow * CDIM + kofs + lcb;
        const uint32_t d0 = (uint32_t)(lrow * SP + lcb) * 2u;
        cpa16(sb + (P16_A * 2u) + d0,      A_ + go0);
        cpa16(sb + (P16_A * 2u) + d0 + 16, A_ + go0 + 8);
        cpa16(sb + (P16_B * 2u) + d0,      B_ + go0);
        cpa16(sb + (P16_B * 2u) + d0 + 16, B_ + go0 + 8);
        cpa_commit();
    };

    float acc[2][8][4];
    #pragma unroll
    for (int i = 0; i < 2; i++)
        #pragma unroll
        for (int j = 0; j < 8; j++)
            #pragma unroll
            for (int q = 0; q < 4; q++) acc[i][j][q] = 0.f;

    const int T = CDIM / BKS;   // 8
    issue(0);

    for (int t = 0; t < T; t++) {
        cpa_wait<0>();
        __syncthreads();
        if (t + 1 < T) issue(t + 1); else cpa_commit();

        const int buf = t % STAGES;
        const uint32_t sb = sbase + (uint32_t)(buf * P16_STG) * 2u;

        #pragma unroll
        for (int ks = 0; ks < 2; ks++) {
            const int kb = ks * 16;
            uint32_t a[2][4];
            #pragma unroll
            for (int mt = 0; mt < 2; mt++) {
                const uint32_t ro = (uint32_t)((wm * 32 + mt * 16 + qrow) * SP + kb + qcol) * 2u;
                ldsm_x4(a[mt][0], a[mt][1], a[mt][2], a[mt][3], sb + P16_A * 2u + ro);
            }
            #pragma unroll
            for (int ng = 0; ng < 4; ng++) {
                const uint32_t bo = (uint32_t)((wn * 64 + ng * 16 + qrow) * SP + kb + qcol) * 2u;
                uint32_t b[4];
                ldsm_x4(b[0], b[1], b[2], b[3], sb + P16_B * 2u + bo);
                #pragma unroll
                for (int sel = 0; sel < 2; sel++) {
                    const int nt = ng * 2 + sel;
                    #pragma unroll
                    for (int mt = 0; mt < 2; mt++) {
                        mma_fp16(acc[mt][nt], a[mt][0], a[mt][1], a[mt][2], a[mt][3],
                                 b[sel], b[sel + 2]);
                    }
                }
            }
        }
    }

    #pragma unroll
    for (int mt = 0; mt < 2; mt++) {
        #pragma unroll
        for (int nt = 0; nt < 8; nt++) {
            const int r0 = m0 + wm * 32 + mt * 16 + lr;
            const int c0 = n0 + wn * 64 + nt * 8 + lc * 2;
            #pragma unroll
            for (int rq = 0; rq < 2; rq++) {
                const int r = r0 + rq * 8;
                const size_t o = (size_t)r * CDIM + c0;
                *(__half2*)(C16 + o) =
                    __floats2half2_rn(acc[mt][nt][rq * 2 + 0], acc[mt][nt][rq * 2 + 1]);
            }
        }
    }
}

// ---------------- scores GEMM: e = Y X^T, 3x-bf16, 128x128 tile ----------------
__global__ void __launch_bounds__(NTHR, 2)
scores_bf16(const __nv_bfloat16* __restrict__ yH, const __nv_bfloat16* __restrict__ yL,
            const __nv_bfloat16* __restrict__ xH, const __nv_bfloat16* __restrict__ xL,
            const int* __restrict__ adj, __half* __restrict__ pt,
            float* __restrict__ pm, float* __restrict__ ps)
{
    extern __shared__ __align__(16) __nv_bfloat16 smb[];
    constexpr int STAGES = 2;

    const int tid  = threadIdx.x;
    const int lane = tid & 31;
    const int warp = tid >> 5;
    const int wm = warp & 3, wn = warp >> 2;
    const int lr = lane >> 2, lc = lane & 3;
    const int n0 = blockIdx.x * BN;
    const int m0 = blockIdx.y * BM;
    const int z  = blockIdx.z;

    const long long BS = (long long)NSEQ * CDIM;
    const __nv_bfloat16* A_H = yH + z * BS + (long long)m0 * CDIM;
    const __nv_bfloat16* A_L = yL + z * BS + (long long)m0 * CDIM;
    const __nv_bfloat16* B_H = xH + z * BS + (long long)n0 * CDIM;
    const __nv_bfloat16* B_L = xL + z * BS + (long long)n0 * CDIM;

    uint32_t sbase = smem_u32(smb);

    const int lrow = tid >> 1;
    const int lcb  = (tid & 1) * 16;
    const int qrow = lane & 15;
    const int qcol = (lane >> 4) << 3;

    auto issue = [&](int t) {
        const int buf = t % STAGES;
        const uint32_t sb = sbase + (uint32_t)(buf * SSTG) * 2u;
        const int kofs = t * BKS;
        const long long go0 = (long long)lrow * CDIM + kofs + lcb;
        const uint32_t d0 = (uint32_t)(lrow * SP + lcb) * 2u;
        cpa16(sb + (SA_H * 2u) + d0,      A_H + go0);
        cpa16(sb + (SA_H * 2u) + d0 + 16, A_H + go0 + 8);
        cpa16(sb + (SA_L * 2u) + d0,      A_L + go0);
        cpa16(sb + (SA_L * 2u) + d0 + 16, A_L + go0 + 8);
        cpa16(sb + (SB_H * 2u) + d0,      B_H + go0);
        cpa16(sb + (SB_H * 2u) + d0 + 16, B_H + go0 + 8);
        cpa16(sb + (SB_L * 2u) + d0,      B_L + go0);
        cpa16(sb + (SB_L * 2u) + d0 + 16, B_L + go0 + 8);
        cpa_commit();
    };

    float acc[2][8][4];
    #pragma unroll
    for (int i = 0; i < 2; i++)
        #pragma unroll
        for (int j = 0; j < 8; j++)
            #pragma unroll
            for (int q = 0; q < 4; q++) acc[i][j][q] = 0.f;

    const int T = CDIM / BKS;   // 8
    issue(0);

    for (int t = 0; t < T; t++) {
        cpa_wait<0>();
        __syncthreads();
        if (t + 1 < T) issue(t + 1); else cpa_commit();

        const int buf = t % STAGES;
        const uint32_t sb = sbase + (uint32_t)(buf * SSTG) * 2u;

        #pragma unroll
        for (int ks = 0; ks < 2; ks++) {
            const int kb = ks * 16;
            uint32_t aH[2][4], aL[2][4];
            #pragma unroll
            for (int mt = 0; mt < 2; mt++) {
                const uint32_t ro = (uint32_t)((wm * 32 + mt * 16 + qrow) * SP + kb + qcol) * 2u;
                ldsm_x4(aH[mt][0], aH[mt][1], aH[mt][2], aH[mt][3], sb + SA_H * 2u + ro);
                ldsm_x4(aL[mt][0], aL[mt][1], aL[mt][2], aL[mt][3], sb + SA_L * 2u + ro);
            }
            #pragma unroll
            for (int ng = 0; ng < 4; ng++) {
                const uint32_t bo = (uint32_t)((wn * 64 + ng * 16 + qrow) * SP + kb + qcol) * 2u;
                uint32_t bh[4], bl[4];
                ldsm_x4(bh[0], bh[1], bh[2], bh[3], sb + SB_H * 2u + bo);
                ldsm_x4(bl[0], bl[1], bl[2], bl[3], sb + SB_L * 2u + bo);
                #pragma unroll
                for (int sel = 0; sel < 2; sel++) {
                    const int nt = ng * 2 + sel;
                    const uint32_t bH0 = bh[sel], bH1 = bh[sel + 2];
                    const uint32_t bL0 = bl[sel], bL1 = bl[sel + 2];
                    #pragma unroll
                    for (int mt = 0; mt < 2; mt++) {
                        mma_bf16(acc[mt][nt], aH[mt][0], aH[mt][1], aH[mt][2], aH[mt][3], bL0, bL1);
                        mma_bf16(acc[mt][nt], aL[mt][0], aL[mt][1], aL[mt][2], aL[mt][3], bH0, bH1);
                        mma_bf16(acc[mt][nt], aH[mt][0], aH[mt][1], aH[mt][2], aH[mt][3], bH0, bH1);
                    }
                }
            }
        }
    }

    // ---- epilogue pass A: leakyrelu + mask into acc, track per-row tile max ----
    float mx[2][2];
    mx[0][0] = mx[0][1] = mx[1][0] = mx[1][1] = -3.0e38f;
    #pragma unroll
    for (int mt = 0; mt < 2; mt++) {
        #pragma unroll
        for (int nt = 0; nt < 8; nt++) {
            const int r0 = m0 + wm * 32 + mt * 16 + lr;
            const int c0 = n0 + wn * 64 + nt * 8 + lc * 2;
            #pragma unroll
            for (int q = 0; q < 4; q++) {
                const int r = r0 + (q >> 1) * 8;
                const int c = c0 + (q & 1);
                float v = acc[mt][nt][q];
                v = (v > 0.f) ? v : ALPHA_SLOPE * v;
                v = (adj[(size_t)r * NSEQ + c] > 0) ? v : NEG_INF_F;
                acc[mt][nt][q] = v;
                mx[mt][q >> 1] = fmaxf(mx[mt][q >> 1], v);
            }
        }
    }

    // ---- tile-row max reduction ----
    float* red = reinterpret_cast<float*>(smb);
    __syncthreads();

    #pragma unroll
    for (int mt = 0; mt < 2; mt++)
        #pragma unroll
        for (int qr = 0; qr < 2; qr++) {
            float v = mx[mt][qr];
            v = fmaxf(v, __shfl_xor_sync(0xffffffffu, v, 1));
            v = fmaxf(v, __shfl_xor_sync(0xffffffffu, v, 2));
            mx[mt][qr] = v;
        }
    if (lc == 0) {
        #pragma unroll
        for (int mt = 0; mt < 2; mt++)
            #pragma unroll
            for (int qr = 0; qr < 2; qr++)
                red[wn * 128 + wm * 32 + mt * 16 + qr * 8 + lr] = mx[mt][qr];
    }
    __syncthreads();
    float M[2][2];
    #pragma unroll
    for (int mt = 0; mt < 2; mt++)
        #pragma unroll
        for (int qr = 0; qr < 2; qr++) {
            const int lro = wm * 32 + mt * 16 + qr * 8 + lr;
            M[mt][qr] = fmaxf(red[lro], red[128 + lro]);
        }
    __syncthreads();

    // ---- pass B: exp, store p_t fp16, accumulate sum partials ----
    __half* Pp = pt + (size_t)z * NSEQ * NSEQ;
    float Ss[2][2];
    #pragma unroll
    for (int mt = 0; mt < 2; mt++)
        #pragma unroll
        for (int qr = 0; qr < 2; qr++) {
            float s = 0.f;
            const int r = m0 + wm * 32 + mt * 16 + qr * 8 + lr;
            #pragma unroll
            for (int nt = 0; nt < 8; nt++) {
                float pe0 = __expf(acc[mt][nt][qr * 2 + 0] - M[mt][qr]);
                float pe1 = __expf(acc[mt][nt][qr * 2 + 1] - M[mt][qr]);
                s += pe0 + pe1;
                const int c = n0 + wn * 64 + nt * 8 + lc * 2;
                *(__half2*)(Pp + (size_t)r * NSEQ + c) = __floats2half2_rn(pe0, pe1);
            }
            s += __shfl_xor_sync(0xffffffffu, s, 1);
            s += __shfl_xor_sync(0xffffffffu, s, 2);
            Ss[mt][qr] = s;
        }
    if (lc == 0) {
        #pragma unroll
        for (int mt = 0; mt < 2; mt++)
            #pragma unroll
            for (int qr = 0; qr < 2; qr++)
                red[wn * 128 + wm * 32 + mt * 16 + qr * 8 + lr] = Ss[mt][qr];
    }
    __syncthreads();
    if (wn == 0 && lc == 0) {
        #pragma unroll
        for (int mt = 0; mt < 2; mt++)
            #pragma unroll
            for (int qr = 0; qr < 2; qr++) {
                const int lro = wm * 32 + mt * 16 + qr * 8 + lr;
                const size_t o = ((size_t)z * NTILES + blockIdx.x) * NSEQ + m0 + lro;
                pm[o] = M[mt][qr];
                ps[o] = red[lro] + red[128 + lro];
            }
    }
}

// ---------------- AV: p_t staged, register-scaled A fragments, fp16 mma ----------------
__global__ void __launch_bounds__(NTHR, 2)
av_fused(const __half* __restrict__ pt, const __half* __restrict__ h3,
         const float* __restrict__ pm, const float* __restrict__ ps,
         float* __restrict__ out)
{
    extern __shared__ __align__(16) uint8_t avs[];

    const int tid  = threadIdx.x;
    const int lane = tid & 31;
    const int warp = tid >> 5;
    const int wm = warp & 1;        // 2 warps over 64 rows
    const int wn = warp >> 1;       // 4 warps over 256 cols
    const int lr = lane >> 2, lc = lane & 3;
    const int m0 = blockIdx.x * AV_BM;
    const int z  = blockIdx.y;

    const __half* Ap = pt + (size_t)z * NSEQ * NSEQ + (size_t)m0 * NSEQ;
    const __half* Bp = h3 + (size_t)z * NSEQ * CDIM;

    uint32_t sbase = smem_u32(avs);

    const int qrow = lane & 15;
    const int qcol = (lane >> 4) << 3;

    // ---- per-row softmax stats + per-(row,tile) scale table (threads 0-63) ----
    __half2* stab = (__half2*)(avs + AV_STAB);
    if (tid < 64) {
        const int rr = tid;
        const float* pmz = pm + (size_t)z * NTILES * NSEQ + m0 + rr;
        const float* psz = ps + (size_t)z * NTILES * NSEQ + m0 + rr;
        float m = -3.0e38f;
        #pragma unroll
        for (int t = 0; t < NTILES; t++) m = fmaxf(m, pmz[(size_t)t * NSEQ]);
        float s = 0.f;
        #pragma unroll
        for (int t = 0; t < NTILES; t++)
            s += psz[(size_t)t * NSEQ] * __expf(pmz[(size_t)t * NSEQ] - m);
        const float inv = 1.0f / s;
        #pragma unroll
        for (int t = 0; t < NTILES; t++)
            stab[rr * NTILES + t] =
                __float2half2_rn(__expf(pmz[(size_t)t * NSEQ] - m) * inv);
    }

    const int crow = tid >> 2;      // 0..63
    const int cq   = tid & 3;

    auto issue = [&](int t) {
        const int buf = t % AV_NSTG;
        const uint32_t sA = sbase + (uint32_t)(buf * AV_STG2);
        const uint32_t sB = sA + AV_A_BYTES;
        const int kofs = t * BKS;
        {
            const __half* src = Ap + (size_t)crow * NSEQ + kofs + cq * 8;
            cpa16(sA + (uint32_t)(crow * APT + cq * 8) * 2u, src);
        }
        {
            const int brow = tid >> 3, bq = tid & 7;
            const __half* src = Bp + (size_t)(kofs + brow) * CDIM + bq * 32;
            const uint32_t d = sB + (uint32_t)(brow * BKP2 + bq * 32) * 2u;
            cpa16(d,      src);
            cpa16(d + 16, src + 8);
            cpa16(d + 32, src + 16);
            cpa16(d + 48, src + 24);
        }
        cpa_commit();
    };

    float acc[2][8][4];
    #pragma unroll
    for (int i = 0; i < 2; i++)
        #pragma unroll
        for (int j = 0; j < 8; j++)
            #pragma unroll
            for (int q = 0; q < 4; q++) acc[i][j][q] = 0.f;

    const int T = NSEQ / BKS;   // 64
    issue(0);
    issue(1);
    issue(2);
    __syncthreads();            // stab + ordering

    for (int t = 0; t < T; t++) {
        cpa_wait<AV_NSTG - 2>();
        __syncthreads();
        if (t + 3 < T) issue(t + 3); else cpa_commit();

        const uint32_t sA = sbase + (uint32_t)((t % AV_NSTG) * AV_STG2);
        const uint32_t sB = sA + AV_A_BYTES;
        const int kt = t >> 2;

        __half2 sc0[2], sc1[2];
        #pragma unroll
        for (int mt = 0; mt < 2; mt++) {
            const int base = wm * 32 + mt * 16;
            sc0[mt] = stab[(base + lr) * NTILES + kt];
            sc1[mt] = stab[(base + 8 + lr) * NTILES + kt];
        }

        #pragma unroll
        for (int ks = 0; ks < 2; ks++) {
            const int kb = ks * 16;
            uint32_t a[2][4];
            #pragma unroll
            for (int mt = 0; mt < 2; mt++) {
                const uint32_t ro = (uint32_t)((wm * 32 + mt * 16 + qrow) * APT + kb + qcol) * 2u;
                ldsm_x4(a[mt][0], a[mt][1], a[mt][2], a[mt][3], sA + ro);
                a[mt][0] = hmul2_u(a[mt][0], sc0[mt]);
                a[mt][2] = hmul2_u(a[mt][2], sc0[mt]);
                a[mt][1] = hmul2_u(a[mt][1], sc1[mt]);
                a[mt][3] = hmul2_u(a[mt][3], sc1[mt]);
            }
            #pragma unroll
            for (int ng = 0; ng < 4; ng++) {
                const int nb = wn * 64 + ng * 16;
                const uint32_t bo = (uint32_t)((kb + qrow) * BKP2 + nb + qcol) * 2u;
                uint32_t b[4];
                ldsm_x4_t(b[0], b[1], b[2], b[3], sB + bo);
                #pragma unroll
                for (int sel = 0; sel < 2; sel++) {
                    const int nt = ng * 2 + sel;
                    #pragma unroll
                    for (int mt = 0; mt < 2; mt++) {
                        mma_fp16(acc[mt][nt], a[mt][0], a[mt][1], a[mt][2], a[mt][3],
                                 b[2 * sel], b[2 * sel + 1]);
                    }
                }
            }
        }
    }

    // ---- epilogue: relu ----
    float* Cp = out + (size_t)z * NSEQ * CDIM;
    #pragma unroll
    for (int mt = 0; mt < 2; mt++) {
        #pragma unroll
        for (int nt = 0; nt < 8; nt++) {
            const int r0 = m0 + wm * 32 + mt * 16 + lr;
            const int c0 = wn * 64 + nt * 8 + lc * 2;
            #pragma unroll
            for (int q = 0; q < 4; q++) {
                const int r = r0 + (q >> 1) * 8;
                const int c = c0 + (q & 1);
                float v = acc[mt][nt][q];
                Cp[(size_t)r * CDIM + c] = (v > 0.f) ? v : 0.f;
            }
        }
    }
}

// ---------------- launcher ----------------
extern "C" void kernel_launch(void* const* d_in, const int* in_sizes, int n_in,
                              void* d_out, int out_size)
{
    const float* inp = (const float*)d_in[0];
    const int*   adj = (const int*)d_in[1];
    const float* W1  = (const float*)d_in[2];
    const float* W2  = (const float*)d_in[3];
    const float* W3  = (const float*)d_in[4];
    float* out = (float*)d_out;

    __nv_bfloat16 *xbH, *xbL, *wtH, *wtL, *hbH, *hbL;
    __half *x16, *w316, *h316, *pt;
    float *pm, *ps;
    cudaGetSymbolAddress((void**)&xbH,  g_xbH);
    cudaGetSymbolAddress((void**)&xbL,  g_xbL);
    cudaGetSymbolAddress((void**)&x16,  g_x16);
    cudaGetSymbolAddress((void**)&wtH,  g_wtH);
    cudaGetSymbolAddress((void**)&wtL,  g_wtL);
    cudaGetSymbolAddress((void**)&w316, g_w316);
    cudaGetSymbolAddress((void**)&hbH,  g_hbH);
    cudaGetSymbolAddress((void**)&hbL,  g_hbL);
    cudaGetSymbolAddress((void**)&h316, g_h316);
    cudaGetSymbolAddress((void**)&pt,   g_pt);
    cudaGetSymbolAddress((void**)&pm,   g_pm);
    cudaGetSymbolAddress((void**)&ps,   g_ps);

    const int SM_BF  = SSTG * 2 * 2;      // 81920 B
    const int SM_P16 = P16_STG * 2 * 2;   // 40960 B
    cudaFuncSetAttribute(proj_bf16,   cudaFuncAttributeMaxDynamicSharedMemorySize, SM_BF);
    cudaFuncSetAttribute(proj_fp16,   cudaFuncAttributeMaxDynamicSharedMemorySize, SM_P16);
    cudaFuncSetAttribute(scores_bf16, cudaFuncAttributeMaxDynamicSharedMemorySize, SM_BF);
    cudaFuncSetAttribute(av_fused,    cudaFuncAttributeMaxDynamicSharedMemorySize, SM_AV);

    // 0) split X (bf16 hi/lo + fp16); gt = (W1 W2^T)^T; w316 = W3^T fp16
    {
        const int xn4 = (int)((size_t)M_ALL * CDIM / 4);
        split_x_bf16<<<(xn4 + 255) / 256, 256>>>(inp, xbH, xbL, x16, xn4);
        dim3 gg(CDIM / 64, CDIM / 64);
        gt_kernel<<<gg, 256>>>(W1, W2, wtH, wtL);
        w316_kernel<<<CDIM * CDIM / 256, 256>>>(W3, w316);
    }
    // 1) projections: Y = X G (3x-bf16); h3 = X W3 (fp16 single pass)
    {
        dim3 g(CDIM / BN, M_ALL / BM);
        proj_bf16<<<g, NTHR, SM_BF>>>(xbH, xbL, wtH, wtL, hbH, hbL);
        proj_fp16<<<g, NTHR, SM_P16>>>(x16, w316, h316);
    }
    // 2) scores: e = Y X^T -> p_t fp16 + per-tile softmax partials
    {
        dim3 g(NSEQ / BN, NSEQ / BM, BB);
        scores_bf16<<<g, NTHR, SM_BF>>>(hbH, hbL, xbH, xbL, adj, pt, pm, ps);
    }
    // 3) AV with staged p_t, register scaling, in-kernel softmax stats
    {
        dim3 g(NSEQ / AV_BM, BB);
        av_fused<<<g, NTHR, SM_AV>>>(pt, h316, pm, ps, out);
    }
}